// round 12
// baseline (speedup 1.0000x reference)
#include <cuda_runtime.h>
#include <cuda_bf16.h>
#include <math.h>
#include <stdint.h>

#define BB 8
#define SS 2048
#define DIMV 240
#define NTOK (BB*SS)          // 16384
#define NEXP 8
#define NDEPTH 8
#define LATENTV 8
#define LOWD 80
#define LNEPS 1e-5f
#define PI_F 3.14159265358979323846f

// ------------------------- device scratch ----------------------------------
__device__ __nv_bfloat16 g_hh[(size_t)NTOK * DIMV];   // h hi (bf16)
__device__ __nv_bfloat16 g_hl[(size_t)NTOK * DIMV];   // h lo (bf16 residual)
__device__ float g_part[2][(size_t)NTOK * DIMV];
__device__ int   g_cnt[NDEPTH][NEXP];
__device__ int   g_list_tok[NEXP][NTOK];
__device__ float g_list_w[NEXP][NTOK];
__device__ int   g_list_k[NEXP][NTOK];
__device__ int   g_route_e[NTOK * 2];
__device__ float g_route_w[NTOK * 2];
__device__ float g_ce[240 * DIMV];
__device__ float g_se[240 * DIMV];
__device__ __nv_bfloat16 g_Bth[(size_t)NDEPTH * NEXP * DIMV * DIMV];
__device__ __nv_bfloat16 g_Btl[(size_t)NDEPTH * NEXP * DIMV * DIMV];

// ------------------------- PTX helpers --------------------------------------
__device__ __forceinline__ unsigned smem_u32(const void* p) {
    return (unsigned)__cvta_generic_to_shared(p);
}
__device__ __forceinline__ void cp16(unsigned dst, const void* src) {
    asm volatile("cp.async.ca.shared.global [%0], [%1], 16;\n" :: "r"(dst), "l"(src));
}
__device__ __forceinline__ void cp_commit() {
    asm volatile("cp.async.commit_group;\n" ::: "memory");
}
template<int N>
__device__ __forceinline__ void cp_wait() {
    asm volatile("cp.async.wait_group %0;\n" :: "n"(N) : "memory");
}
__device__ __forceinline__ void ldsm4(uint32_t* r, uint32_t addr) {
    asm volatile("ldmatrix.sync.aligned.m8n8.x4.shared.b16 {%0,%1,%2,%3}, [%4];"
                 : "=r"(r[0]), "=r"(r[1]), "=r"(r[2]), "=r"(r[3]) : "r"(addr));
}
#define MMA_BF16(dd, A0, A1, A2, A3, B0, B1)                                   \
    asm volatile("mma.sync.aligned.m16n8k16.row.col.f32.bf16.bf16.f32 "        \
                 "{%0,%1,%2,%3},{%4,%5,%6,%7},{%8,%9},{%0,%1,%2,%3};"          \
                 : "+f"((dd)[0]), "+f"((dd)[1]), "+f"((dd)[2]), "+f"((dd)[3])  \
                 : "r"(A0), "r"(A1), "r"(A2), "r"(A3), "r"(B0), "r"(B1))

// ------------------------- routing finalize (one thread) --------------------
__device__ __forceinline__ void route_finalize(const float l[8], int L, int tok) {
    int e0 = 0; float b0 = l[0];
#pragma unroll
    for (int q = 1; q < 8; q++)
        if (l[q] > b0) { b0 = l[q]; e0 = q; }
    int e1 = -1; float b1 = -1e30f;
#pragma unroll
    for (int q = 0; q < 8; q++)
        if (q != e0 && l[q] > b1) { b1 = l[q]; e1 = q; }

    float w0 = 1.0f / (1.0f + expf(b1 - b0));
    float w1 = 1.0f - w0;

    int p0 = atomicAdd(&g_cnt[L][e0], 1);
    g_list_tok[e0][p0] = tok; g_list_w[e0][p0] = w0; g_list_k[e0][p0] = 0;
    int p1 = atomicAdd(&g_cnt[L][e1], 1);
    g_list_tok[e1][p1] = tok; g_list_w[e1][p1] = w1; g_list_k[e1][p1] = 1;

    g_route_e[tok * 2 + 0] = e0; g_route_e[tok * 2 + 1] = e1;
    g_route_w[tok * 2 + 0] = w0; g_route_w[tok * 2 + 1] = w1;
}

// ------------------------- setup: emb tables + counter zero -----------------
__global__ void setup_kernel(const float* __restrict__ roots,
                             const float* __restrict__ projW) {
    int s = blockIdx.x;
    int d = threadIdx.x;
    int j = d % LOWD;
    float emb = 0.f;
#pragma unroll
    for (int i = 0; i < LATENTV; i++)
        emb += roots[s * LATENTV + i] * projW[i * LOWD + j];
    g_ce[s * DIMV + d] = cosf(emb);
    g_se[s * DIMV + d] = sinf(emb);
    if (blockIdx.x == 0 && d < NDEPTH * NEXP)
        ((int*)g_cnt)[d] = 0;
}

// ------------------------- B convert + transpose ----------------------------
__global__ void bconv_kernel(const float* __restrict__ eW) {
    int le = blockIdx.y;
    int k0 = blockIdx.x * 16;
    const float* W = eW + (size_t)le * DIMV * DIMV;
    __nv_bfloat16* BH = g_Bth + (size_t)le * DIMV * DIMV;
    __nv_bfloat16* BL = g_Btl + (size_t)le * DIMV * DIMV;
    __shared__ float tile[16][241];
    for (int i = threadIdx.x; i < 16 * 240; i += 256) {
        int kk = i / 240, n = i - kk * 240;
        tile[kk][n] = W[(size_t)(k0 + kk) * DIMV + n];
    }
    __syncthreads();
    for (int i = threadIdx.x; i < 240 * 16; i += 256) {
        int n = i >> 4, kk = i & 15;
        float v = tile[kk][n];
        __nv_bfloat16 h = __float2bfloat16(v);
        float r = v - __bfloat162float(h);
        BH[(size_t)n * DIMV + k0 + kk] = h;
        BL[(size_t)n * DIMV + k0 + kk] = __float2bfloat16(r);
    }
}

// ------------------------- cycle block + fused gate(0) ----------------------
__global__ void cycle_kernel(const float* __restrict__ x,
                             const int* __restrict__ step,
                             const float* __restrict__ gW,
                             const float* __restrict__ gb) {
    __shared__ float s_x1[DIMV];
    __shared__ float s_se[DIMV];
    __shared__ float s_pump;
    __shared__ float s_acc[8];
    int t = blockIdx.x;
    int d = threadIdx.x;
    int lane = d & 31;
    int r = (t % SS) % 240;
    if (d == 0) s_pump = 0.8f * sinf((float)(*step) * 0.006f * 2.0f * PI_F);
    if (d < 8) s_acc[d] = 0.f;
    float ce = 0.f, se = 0.f;
    if (d < DIMV) {
        ce = g_ce[r * DIMV + d];
        se = g_se[r * DIMV + d];
        s_se[d] = se;
    }
    __syncthreads();
    if (d < DIMV)
        s_x1[d] = x[(size_t)t * DIMV + d] * (ce + s_pump);
    __syncthreads();

    float h = 0.f;
    if (d < DIMV) {
        int dm1 = (d + DIMV - 1) % DIMV;
        int dm2 = (d + DIMV - 2) % DIMV;
        h = (s_x1[d]
           + s_x1[dm1] * se
           + s_x1[dm2] * s_se[dm1] * ce) * (1.0f / 3.0f);
        __nv_bfloat16 hi = __float2bfloat16(h);
        g_hh[(size_t)t * DIMV + d] = hi;
        g_hl[(size_t)t * DIMV + d] = __float2bfloat16(h - __bfloat162float(hi));
    }

    float p[8];
    if (d < DIMV) {
        float4 w0 = *(const float4*)&gW[d * 8];
        float4 w1 = *(const float4*)&gW[d * 8 + 4];
        p[0] = h * w0.x; p[1] = h * w0.y; p[2] = h * w0.z; p[3] = h * w0.w;
        p[4] = h * w1.x; p[5] = h * w1.y; p[6] = h * w1.z; p[7] = h * w1.w;
    } else {
#pragma unroll
        for (int e = 0; e < 8; e++) p[e] = 0.f;
    }
#pragma unroll
    for (int e = 0; e < 8; e++)
#pragma unroll
        for (int o = 16; o > 0; o >>= 1)
            p[e] += __shfl_xor_sync(0xffffffffu, p[e], o);
    if (lane == 0) {
#pragma unroll
        for (int e = 0; e < 8; e++)
            atomicAdd(&s_acc[e], p[e]);
    }
    __syncthreads();
    if (d == 0) {
        float l[8];
#pragma unroll
        for (int e = 0; e < 8; e++) l[e] = s_acc[e] + gb[e];
        route_finalize(l, 0, t);
    }
}

// ------------------------- gate helper (warp; h in registers) ---------------
__device__ __forceinline__ void gate_from_regs(const float hh[8],
                                               const float* __restrict__ gW,
                                               const float* __restrict__ gb,
                                               int L, int tok, int lane) {
    float acc[8];
#pragma unroll
    for (int e = 0; e < 8; e++) acc[e] = 0.f;
#pragma unroll
    for (int jq = 0; jq < 8; jq++) {
        int d = lane + 32 * jq;
        if (d < DIMV) {
            float hv = hh[jq];
            float4 w0 = *(const float4*)&gW[d * 8];
            float4 w1 = *(const float4*)&gW[d * 8 + 4];
            acc[0] += hv * w0.x; acc[1] += hv * w0.y;
            acc[2] += hv * w0.z; acc[3] += hv * w0.w;
            acc[4] += hv * w1.x; acc[5] += hv * w1.y;
            acc[6] += hv * w1.z; acc[7] += hv * w1.w;
        }
    }
#pragma unroll
    for (int e = 0; e < 8; e++)
#pragma unroll
        for (int o = 16; o > 0; o >>= 1)
            acc[e] += __shfl_xor_sync(0xffffffffu, acc[e], o);

    if (lane == 0) {
        float l[8];
#pragma unroll
        for (int e = 0; e < 8; e++) l[e] = acc[e] + gb[e];
        route_finalize(l, L, tok);
    }
}

// ------------------------- tensor-core grouped GEMM (mma.sync bf16) ---------
// MT=128 x 240, KC=48 double buffered; 384 threads = 12 warps:
// wm = wid&3 (32 rows, two 16-row m-tiles), wn = wid>>2 (80 cols, 10 n-tiles).
// MMA terms issued term-major for acc-RAW spacing.
#define MT 128
#define NTILES (2 * NTOK / MT + NEXP)   // 264
#define KC 48
#define AST 56                           // smem row stride in bf16 (112 B)
#define ASTB (AST * 2)                   // 112 bytes
#define OFF_AH 0                         // [2][128][56] bf16 = 28672
#define OFF_AL 28672
#define OFF_BH 57344                     // [2][240][56] bf16 = 53760
#define OFF_BL 111104
#define SMEM_DYN 164864
#define ASTAGE (MT * ASTB)               // 14336
#define BSTAGE (DIMV * ASTB)             // 26880
#define GTHR 384

__global__ __launch_bounds__(GTHR, 1)
void moe_mma_kernel(int L) {
    int tileid = blockIdx.x;
    int e = 0, base = 0, cnt = 0, cum = 0;
#pragma unroll
    for (int q = 0; q < NEXP; q++) {
        int cq = g_cnt[L][q];
        int t = (cq + MT - 1) / MT;
        if (tileid >= cum && tileid < cum + t) { e = q; base = (tileid - cum) * MT; cnt = cq; }
        cum += t;
    }
    if (tileid >= cum) return;
    int mr = min(MT, cnt - base);

    extern __shared__ __align__(16) char dsm[];
    __shared__ int   s_tok[MT];
    __shared__ float s_w[MT];
    __shared__ int   s_k[MT];

    int tid = threadIdx.x, wid = tid >> 5, lane = tid & 31;

    if (tid < MT) {
        if (tid < mr) {
            s_tok[tid] = g_list_tok[e][base + tid];
            s_w[tid]   = g_list_w[e][base + tid];
            s_k[tid]   = g_list_k[e][base + tid];
        } else { s_tok[tid] = 0; s_w[tid] = 0.f; s_k[tid] = 0; }
    }
    __syncthreads();

    const __nv_bfloat16* BHsrc = g_Bth + (size_t)(L * NEXP + e) * DIMV * DIMV;
    const __nv_bfloat16* BLsrc = g_Btl + (size_t)(L * NEXP + e) * DIMV * DIMV;

    auto issue = [&](int kc, int buf) {
        int abuf = buf * ASTAGE;
        int bbuf = buf * BSTAGE;
#pragma unroll
        for (int j = 0; j < 2; j++) {                 // A: 128 rows x 6 segs = 768
            int i = tid + j * GTHR;
            int row = i / 6, seg = i - row * 6;
            size_t src = (size_t)s_tok[row] * DIMV + kc * KC + seg * 8;
            unsigned dst = row * ASTB + seg * 16;
            cp16(smem_u32(dsm + OFF_AH + abuf + dst), g_hh + src);
            cp16(smem_u32(dsm + OFF_AL + abuf + dst), g_hl + src);
        }
        for (int i = tid; i < DIMV * 6; i += GTHR) {  // B: 240 rows x 6 segs = 1440
            int row = i / 6, seg = i - row * 6;
            size_t src = (size_t)row * DIMV + kc * KC + seg * 8;
            unsigned dst = row * ASTB + seg * 16;
            cp16(smem_u32(dsm + OFF_BH + bbuf + dst), BHsrc + src);
            cp16(smem_u32(dsm + OFF_BL + bbuf + dst), BLsrc + src);
        }
        cp_commit();
    };

    int wm = wid & 3;     // 32-row group (two 16-row m-tiles)
    int wn = wid >> 2;    // 80-col n-third (10 n-tiles)

    float acc[2][10][4];
#pragma unroll
    for (int t = 0; t < 2; t++)
#pragma unroll
        for (int nt = 0; nt < 10; nt++)
#pragma unroll
            for (int j = 0; j < 4; j++) acc[t][nt][j] = 0.f;

    issue(0, 0);

    uint32_t sbase = smem_u32(dsm);
    // A x4: row = wm*32 + t*16 + (lane&15); +16B for lanes>=16 (k half)
    uint32_t a_off = (uint32_t)(wm * 32 + (lane & 15)) * ASTB + ((lane >> 4) << 4);
    // B x4 (2 n-tiles per ldsm4): n = wn*80 + nt2*16 + ((lane>>4)<<3) + (lane&7)
    uint32_t b_off = (uint32_t)(wn * 80 + ((lane >> 4) << 3) + (lane & 7)) * ASTB
                   + (((lane >> 3) & 1) << 4);

    for (int kc = 0; kc < 5; kc++) {
        int buf = kc & 1;
        if (kc + 1 < 5) { issue(kc + 1, buf ^ 1); cp_wait<1>(); }
        else            { cp_wait<0>(); }
        __syncthreads();

        uint32_t AhB = sbase + OFF_AH + buf * ASTAGE;
        uint32_t AlB = sbase + OFF_AL + buf * ASTAGE;
        uint32_t BhB = sbase + OFF_BH + buf * BSTAGE;
        uint32_t BlB = sbase + OFF_BL + buf * BSTAGE;

#pragma unroll
        for (int ks = 0; ks < 3; ks++) {
            uint32_t ah[2][4], al[2][4];
#pragma unroll
            for (int t = 0; t < 2; t++) {
                uint32_t ao = a_off + t * (16 * ASTB) + ks * 32;
                ldsm4(ah[t], AhB + ao);
                ldsm4(al[t], AlB + ao);
            }
#pragma unroll
            for (int nt2 = 0; nt2 < 5; nt2++) {
                uint32_t bo = b_off + nt2 * (16 * ASTB) + ks * 32;
                uint32_t bh[4], bl[4];
                ldsm4(bh, BhB + bo);
                ldsm4(bl, BlB + bo);
                int c0 = 2 * nt2, c1 = 2 * nt2 + 1;
                // term-major ordering: same-acc MMAs spaced 4 apart
                MMA_BF16(acc[0][c0], ah[0][0], ah[0][1], ah[0][2], ah[0][3], bh[0], bh[1]);
                MMA_BF16(acc[0][c1], ah[0][0], ah[0][1], ah[0][2], ah[0][3], bh[2], bh[3]);
                MMA_BF16(acc[1][c0], ah[1][0], ah[1][1], ah[1][2], ah[1][3], bh[0], bh[1]);
                MMA_BF16(acc[1][c1], ah[1][0], ah[1][1], ah[1][2], ah[1][3], bh[2], bh[3]);
                MMA_BF16(acc[0][c0], ah[0][0], ah[0][1], ah[0][2], ah[0][3], bl[0], bl[1]);
                MMA_BF16(acc[0][c1], ah[0][0], ah[0][1], ah[0][2], ah[0][3], bl[2], bl[3]);
                MMA_BF16(acc[1][c0], ah[1][0], ah[1][1], ah[1][2], ah[1][3], bl[0], bl[1]);
                MMA_BF16(acc[1][c1], ah[1][0], ah[1][1], ah[1][2], ah[1][3], bl[2], bl[3]);
                MMA_BF16(acc[0][c0], al[0][0], al[0][1], al[0][2], al[0][3], bh[0], bh[1]);
                MMA_BF16(acc[0][c1], al[0][0], al[0][1], al[0][2], al[0][3], bh[2], bh[3]);
                MMA_BF16(acc[1][c0], al[1][0], al[1][1], al[1][2], al[1][3], bh[0], bh[1]);
                MMA_BF16(acc[1][c1], al[1][0], al[1][1], al[1][2], al[1][3], bh[2], bh[3]);
            }
        }
        __syncthreads();
    }

    // ---- scaled stores straight from fragments ----
#pragma unroll
    for (int t = 0; t < 2; t++) {
        int r0 = wm * 32 + t * 16 + (lane >> 2);
        int r1 = r0 + 8;
        int colb = wn * 80 + (lane & 3) * 2;
        bool ok0 = r0 < mr, ok1 = r1 < mr;
        float w0v = s_w[r0], w1v = s_w[r1];
        float* d0 = ok0 ? &g_part[s_k[r0]][(size_t)s_tok[r0] * DIMV] : 0;
        float* d1 = ok1 ? &g_part[s_k[r1]][(size_t)s_tok[r1] * DIMV] : 0;
#pragma unroll
        for (int nt = 0; nt < 10; nt++) {
            int col = colb + nt * 8;
            if (ok0) {
                float2 o; o.x = w0v * acc[t][nt][0]; o.y = w0v * acc[t][nt][1];
                *(float2*)&d0[col] = o;
            }
            if (ok1) {
                float2 o; o.x = w1v * acc[t][nt][2]; o.y = w1v * acc[t][nt][3];
                *(float2*)&d1[col] = o;
            }
        }
    }
}

// ------------- fused: epilogue(L) [+ gate(L+1) if DO_GATE] -------------------
template<int DO_GATE>
__global__ void epi_gate_kernel(const float* __restrict__ eb,
                                const float* __restrict__ gamma,
                                const float* __restrict__ beta,
                                const float* __restrict__ gW,
                                const float* __restrict__ gb,
                                int Lnext) {
    int warp = threadIdx.x >> 5;
    int lane = threadIdx.x & 31;
    int tok  = blockIdx.x * 8 + warp;

    int   e0 = g_route_e[tok * 2 + 0], e1 = g_route_e[tok * 2 + 1];
    float w0 = g_route_w[tok * 2 + 0], w1 = g_route_w[tok * 2 + 1];

    const float* p0 = &g_part[0][(size_t)tok * DIMV];
    const float* p1 = &g_part[1][(size_t)tok * DIMV];

    float v[8];
    float sum = 0.f;
#pragma unroll
    for (int jq = 0; jq < 8; jq++) {
        int d = lane + 32 * jq;
        if (d < DIMV) {
            v[jq] = p0[d] + p1[d] + w0 * eb[e0 * DIMV + d] + w1 * eb[e1 * DIMV + d];
            sum += v[jq];
        } else v[jq] = 0.f;
    }
#pragma unroll
    for (int o = 16; o > 0; o >>= 1) sum += __shfl_xor_sync(0xffffffffu, sum, o);
    float mean = sum * (1.0f / DIMV);

    float vs = 0.f;
#pragma unroll
    for (int jq = 0; jq < 8; jq++) {
        int d = lane + 32 * jq;
        if (d < DIMV) { float c = v[jq] - mean; vs += c * c; }
    }
#pragma unroll
    for (int o = 16; o > 0; o >>= 1) vs += __shfl_xor_sync(0xffffffffu, vs, o);
    float inv = 1.0f / sqrtf(vs * (1.0f / DIMV) + LNEPS);

    float hh[8];
    __nv_bfloat16* hph = &g_hh[(size_t)tok * DIMV];
    __nv_bfloat16* hpl = &g_hl[(size_t)tok * DIMV];
#pragma unroll
    for (int jq = 0; jq < 8; jq++) {
        int d = lane + 32 * jq;
        if (d < DIMV) {
            float ln = (v[jq] - mean) * inv * gamma[d] + beta[d];
            float hv = v[jq] + ln;
            hh[jq] = hv;
            __nv_bfloat16 hi = __float2bfloat16(hv);
            hph[d] = hi;
            hpl[d] = __float2bfloat16(hv - __bfloat162float(hi));
        } else hh[jq] = 0.f;
    }

    if (DO_GATE)
        gate_from_regs(hh, gW, gb, Lnext, tok, lane);
}

// ------------------------- head (h = hi + lo) --------------------------------
__global__ void head_kernel(const float* __restrict__ hW,
                            const float* __restrict__ hb,
                            float* __restrict__ out) {
    int b = blockIdx.x;
    int tid = threadIdx.x;
    const __nv_bfloat16* hh = g_hh + (size_t)b * SS * DIMV;
    const __nv_bfloat16* hl = g_hl + (size_t)b * SS * DIMV;
    float acc = 0.f;
    for (int i = tid; i < SS * DIMV; i += 256) {
        float h = __bfloat162float(hh[i]) + __bfloat162float(hl[i]);
        acc += h * hW[i % DIMV];
    }
    __shared__ float red[256];
    red[tid] = acc;
    __syncthreads();
    for (int s2 = 128; s2 > 0; s2 >>= 1) {
        if (tid < s2) red[tid] += red[tid + s2];
        __syncthreads();
    }
    if (tid == 0) {
        float z = red[0] * (1.0f / SS) + hb[0];
        out[b] = 1.0f / (1.0f + expf(-z));
    }
}

// ------------------------- launch -------------------------------------------
extern "C" void kernel_launch(void* const* d_in, const int* in_sizes, int n_in,
                              void* d_out, int out_size) {
    const float* x     = (const float*)d_in[0];
    const int*   step  = (const int*)  d_in[1];
    const float* roots = (const float*)d_in[2];
    const float* projW = (const float*)d_in[3];
    const float* gW    = (const float*)d_in[4];
    const float* gb    = (const float*)d_in[5];
    const float* eW    = (const float*)d_in[6];
    const float* ebias = (const float*)d_in[7];
    const float* gamma = (const float*)d_in[8];
    const float* beta  = (const float*)d_in[9];
    const float* hW    = (const float*)d_in[10];
    const float* hb    = (const float*)d_in[11];
    float* out = (float*)d_out;

    cudaFuncSetAttribute(moe_mma_kernel,
                         cudaFuncAttributeMaxDynamicSharedMemorySize, SMEM_DYN);

    setup_kernel<<<240, DIMV>>>(roots, projW);
    {
        dim3 bg(15, NDEPTH * NEXP);
        bconv_kernel<<<bg, 256>>>(eW);
    }
    cycle_kernel<<<NTOK, 256>>>(x, step, gW, gb);

    for (int L = 0; L < NDEPTH; L++) {
        moe_mma_kernel<<<NTILES, GTHR, SMEM_DYN>>>(L);
        if (L + 1 < NDEPTH) {
            epi_gate_kernel<1><<<NTOK / 8, 256>>>(
                ebias + (size_t)L * NEXP * DIMV, gamma, beta,
                gW + (size_t)(L + 1) * DIMV * NEXP, gb + (size_t)(L + 1) * NEXP,
                L + 1);
        } else {
            epi_gate_kernel<0><<<NTOK / 8, 256>>>(
                ebias + (size_t)L * NEXP * DIMV, gamma, beta,
                gW, gb, 0);
        }
    }

    head_kernel<<<BB, 256>>>(hW, hb, out);
}

// round 13
// speedup vs baseline: 1.1143x; 1.1143x over previous
#include <cuda_runtime.h>
#include <cuda_bf16.h>
#include <math.h>
#include <stdint.h>

#define BB 8
#define SS 2048
#define DIMV 240
#define NTOK (BB*SS)          // 16384
#define NEXP 8
#define NDEPTH 8
#define LATENTV 8
#define LOWD 80
#define LNEPS 1e-5f
#define PI_F 3.14159265358979323846f

// ------------------------- device scratch ----------------------------------
__device__ __nv_bfloat16 g_hh[(size_t)NTOK * DIMV];
__device__ __nv_bfloat16 g_hl[(size_t)NTOK * DIMV];
__device__ float g_part[2][(size_t)NTOK * DIMV];
__device__ int   g_cnt[NDEPTH][NEXP];
__device__ int   g_list_tok[NEXP][NTOK];
__device__ float g_list_w[NEXP][NTOK];
__device__ int   g_list_k[NEXP][NTOK];
__device__ int   g_route_e[NTOK * 2];
__device__ float g_route_w[NTOK * 2];
__device__ float g_ce[240 * DIMV];
__device__ float g_se[240 * DIMV];
__device__ __nv_bfloat16 g_Bth[(size_t)NDEPTH * NEXP * DIMV * DIMV];
__device__ __nv_bfloat16 g_Btl[(size_t)NDEPTH * NEXP * DIMV * DIMV];

// ------------------------- PTX helpers --------------------------------------
__device__ __forceinline__ unsigned smem_u32(const void* p) {
    return (unsigned)__cvta_generic_to_shared(p);
}
__device__ __forceinline__ void cp16(unsigned dst, const void* src) {
    asm volatile("cp.async.ca.shared.global [%0], [%1], 16;\n" :: "r"(dst), "l"(src));
}
__device__ __forceinline__ void cp_commit() {
    asm volatile("cp.async.commit_group;\n" ::: "memory");
}
template<int N>
__device__ __forceinline__ void cp_wait() {
    asm volatile("cp.async.wait_group %0;\n" :: "n"(N) : "memory");
}
__device__ __forceinline__ void ldsm4(uint32_t* r, uint32_t addr) {
    asm volatile("ldmatrix.sync.aligned.m8n8.x4.shared.b16 {%0,%1,%2,%3}, [%4];"
                 : "=r"(r[0]), "=r"(r[1]), "=r"(r[2]), "=r"(r[3]) : "r"(addr));
}
__device__ __forceinline__ void ldsm2(uint32_t* r, uint32_t addr) {
    asm volatile("ldmatrix.sync.aligned.m8n8.x2.shared.b16 {%0,%1}, [%2];"
                 : "=r"(r[0]), "=r"(r[1]) : "r"(addr));
}
#define MMA_BF16(dd, A0, A1, A2, A3, B0, B1)                                   \
    asm volatile("mma.sync.aligned.m16n8k16.row.col.f32.bf16.bf16.f32 "        \
                 "{%0,%1,%2,%3},{%4,%5,%6,%7},{%8,%9},{%0,%1,%2,%3};"          \
                 : "+f"((dd)[0]), "+f"((dd)[1]), "+f"((dd)[2]), "+f"((dd)[3])  \
                 : "r"(A0), "r"(A1), "r"(A2), "r"(A3), "r"(B0), "r"(B1))

// ------------------------- routing finalize (one thread) --------------------
__device__ __forceinline__ void route_finalize(const float l[8], int L, int tok) {
    int e0 = 0; float b0 = l[0];
#pragma unroll
    for (int q = 1; q < 8; q++)
        if (l[q] > b0) { b0 = l[q]; e0 = q; }
    int e1 = -1; float b1 = -1e30f;
#pragma unroll
    for (int q = 0; q < 8; q++)
        if (q != e0 && l[q] > b1) { b1 = l[q]; e1 = q; }

    float w0 = 1.0f / (1.0f + expf(b1 - b0));
    float w1 = 1.0f - w0;

    int p0 = atomicAdd(&g_cnt[L][e0], 1);
    g_list_tok[e0][p0] = tok; g_list_w[e0][p0] = w0; g_list_k[e0][p0] = 0;
    int p1 = atomicAdd(&g_cnt[L][e1], 1);
    g_list_tok[e1][p1] = tok; g_list_w[e1][p1] = w1; g_list_k[e1][p1] = 1;

    g_route_e[tok * 2 + 0] = e0; g_route_e[tok * 2 + 1] = e1;
    g_route_w[tok * 2 + 0] = w0; g_route_w[tok * 2 + 1] = w1;
}

// ------------------------- setup: emb tables + counter zero -----------------
__global__ void setup_kernel(const float* __restrict__ roots,
                             const float* __restrict__ projW) {
    int s = blockIdx.x;
    int d = threadIdx.x;
    int j = d % LOWD;
    float emb = 0.f;
#pragma unroll
    for (int i = 0; i < LATENTV; i++)
        emb += roots[s * LATENTV + i] * projW[i * LOWD + j];
    g_ce[s * DIMV + d] = cosf(emb);
    g_se[s * DIMV + d] = sinf(emb);
    if (blockIdx.x == 0 && d < NDEPTH * NEXP)
        ((int*)g_cnt)[d] = 0;
}

// ------------------------- B convert + transpose ----------------------------
__global__ void bconv_kernel(const float* __restrict__ eW) {
    int le = blockIdx.y;
    int k0 = blockIdx.x * 16;
    const float* W = eW + (size_t)le * DIMV * DIMV;
    __nv_bfloat16* BH = g_Bth + (size_t)le * DIMV * DIMV;
    __nv_bfloat16* BL = g_Btl + (size_t)le * DIMV * DIMV;
    __shared__ float tile[16][241];
    for (int i = threadIdx.x; i < 16 * 240; i += 256) {
        int kk = i / 240, n = i - kk * 240;
        tile[kk][n] = W[(size_t)(k0 + kk) * DIMV + n];
    }
    __syncthreads();
    for (int i = threadIdx.x; i < 240 * 16; i += 256) {
        int n = i >> 4, kk = i & 15;
        float v = tile[kk][n];
        __nv_bfloat16 h = __float2bfloat16(v);
        float r = v - __bfloat162float(h);
        BH[(size_t)n * DIMV + k0 + kk] = h;
        BL[(size_t)n * DIMV + k0 + kk] = __float2bfloat16(r);
    }
}

// ------------------------- cycle block + fused gate(0) ----------------------
__global__ void cycle_kernel(const float* __restrict__ x,
                             const int* __restrict__ step,
                             const float* __restrict__ gW,
                             const float* __restrict__ gb) {
    __shared__ float s_x1[DIMV];
    __shared__ float s_se[DIMV];
    __shared__ float s_pump;
    __shared__ float s_acc[8];
    int t = blockIdx.x;
    int d = threadIdx.x;
    int lane = d & 31;
    int r = (t % SS) % 240;
    if (d == 0) s_pump = 0.8f * sinf((float)(*step) * 0.006f * 2.0f * PI_F);
    if (d < 8) s_acc[d] = 0.f;
    float ce = 0.f, se = 0.f;
    if (d < DIMV) {
        ce = g_ce[r * DIMV + d];
        se = g_se[r * DIMV + d];
        s_se[d] = se;
    }
    __syncthreads();
    if (d < DIMV)
        s_x1[d] = x[(size_t)t * DIMV + d] * (ce + s_pump);
    __syncthreads();

    float h = 0.f;
    if (d < DIMV) {
        int dm1 = (d + DIMV - 1) % DIMV;
        int dm2 = (d + DIMV - 2) % DIMV;
        h = (s_x1[d]
           + s_x1[dm1] * se
           + s_x1[dm2] * s_se[dm1] * ce) * (1.0f / 3.0f);
        __nv_bfloat16 hi = __float2bfloat16(h);
        g_hh[(size_t)t * DIMV + d] = hi;
        g_hl[(size_t)t * DIMV + d] = __float2bfloat16(h - __bfloat162float(hi));
    }

    float p[8];
    if (d < DIMV) {
        float4 w0 = *(const float4*)&gW[d * 8];
        float4 w1 = *(const float4*)&gW[d * 8 + 4];
        p[0] = h * w0.x; p[1] = h * w0.y; p[2] = h * w0.z; p[3] = h * w0.w;
        p[4] = h * w1.x; p[5] = h * w1.y; p[6] = h * w1.z; p[7] = h * w1.w;
    } else {
#pragma unroll
        for (int e = 0; e < 8; e++) p[e] = 0.f;
    }
#pragma unroll
    for (int e = 0; e < 8; e++)
#pragma unroll
        for (int o = 16; o > 0; o >>= 1)
            p[e] += __shfl_xor_sync(0xffffffffu, p[e], o);
    if (lane == 0) {
#pragma unroll
        for (int e = 0; e < 8; e++)
            atomicAdd(&s_acc[e], p[e]);
    }
    __syncthreads();
    if (d == 0) {
        float l[8];
#pragma unroll
        for (int e = 0; e < 8; e++) l[e] = s_acc[e] + gb[e];
        route_finalize(l, 0, t);
    }
}

// ------------------------- tensor-core grouped GEMM (mma.sync bf16) ---------
// R11 best-measured config, verbatim: MT=128, KC=48, 256 thr, ldmatrix.
#define MT 128
#define NTILES (2 * NTOK / MT + NEXP)   // 264
#define KC 48
#define AST 56
#define ASTB (AST * 2)                   // 112 bytes
#define OFF_AH 0
#define OFF_AL 28672
#define OFF_BH 57344
#define OFF_BL 111104
#define SMEM_DYN 164864
#define ASTAGE (MT * ASTB)
#define BSTAGE (DIMV * ASTB)

__global__ __launch_bounds__(256, 1)
void moe_mma_kernel(int L) {
    int tileid = blockIdx.x;
    int e = 0, base = 0, cnt = 0, cum = 0;
#pragma unroll
    for (int q = 0; q < NEXP; q++) {
        int cq = g_cnt[L][q];
        int t = (cq + MT - 1) / MT;
        if (tileid >= cum && tileid < cum + t) { e = q; base = (tileid - cum) * MT; cnt = cq; }
        cum += t;
    }
    if (tileid >= cum) return;
    int mr = min(MT, cnt - base);

    extern __shared__ __align__(16) char dsm[];
    __shared__ int   s_tok[MT];
    __shared__ float s_w[MT];
    __shared__ int   s_k[MT];

    int tid = threadIdx.x, wid = tid >> 5, lane = tid & 31;

    if (tid < MT) {
        if (tid < mr) {
            s_tok[tid] = g_list_tok[e][base + tid];
            s_w[tid]   = g_list_w[e][base + tid];
            s_k[tid]   = g_list_k[e][base + tid];
        } else { s_tok[tid] = 0; s_w[tid] = 0.f; s_k[tid] = 0; }
    }
    __syncthreads();

    const __nv_bfloat16* BHsrc = g_Bth + (size_t)(L * NEXP + e) * DIMV * DIMV;
    const __nv_bfloat16* BLsrc = g_Btl + (size_t)(L * NEXP + e) * DIMV * DIMV;

    auto issue = [&](int kc, int buf) {
        int abuf = buf * ASTAGE;
        int bbuf = buf * BSTAGE;
#pragma unroll
        for (int j = 0; j < 3; j++) {
            int i = tid + j * 256;
            int row = i / 6, seg = i - row * 6;
            size_t src = (size_t)s_tok[row] * DIMV + kc * KC + seg * 8;
            unsigned dst = row * ASTB + seg * 16;
            cp16(smem_u32(dsm + OFF_AH + abuf + dst), g_hh + src);
            cp16(smem_u32(dsm + OFF_AL + abuf + dst), g_hl + src);
        }
        for (int i = tid; i < DIMV * 6; i += 256) {
            int row = i / 6, seg = i - row * 6;
            size_t src = (size_t)row * DIMV + kc * KC + seg * 8;
            unsigned dst = row * ASTB + seg * 16;
            cp16(smem_u32(dsm + OFF_BH + bbuf + dst), BHsrc + src);
            cp16(smem_u32(dsm + OFF_BL + bbuf + dst), BLsrc + src);
        }
        cp_commit();
    };

    int wm = wid & 3;
    int wn = wid >> 2;

    float acc[2][15][4];
#pragma unroll
    for (int t = 0; t < 2; t++)
#pragma unroll
        for (int nt = 0; nt < 15; nt++)
#pragma unroll
            for (int j = 0; j < 4; j++) acc[t][nt][j] = 0.f;

    issue(0, 0);

    uint32_t sbase = smem_u32(dsm);
    uint32_t a_off = (uint32_t)(wm * 32 + (lane & 15)) * ASTB + ((lane >> 4) << 4);
    uint32_t b_off = (uint32_t)(wn * 120 + ((lane >> 4) << 3) + (lane & 7)) * ASTB
                   + (((lane >> 3) & 1) << 4);
    uint32_t b2_off = (uint32_t)(wn * 120 + 112 + (lane & 7)) * ASTB
                    + (((lane >> 3) & 1) << 4);

    for (int kc = 0; kc < 5; kc++) {
        int buf = kc & 1;
        if (kc + 1 < 5) { issue(kc + 1, buf ^ 1); cp_wait<1>(); }
        else            { cp_wait<0>(); }
        __syncthreads();

        uint32_t AhB = sbase + OFF_AH + buf * ASTAGE;
        uint32_t AlB = sbase + OFF_AL + buf * ASTAGE;
        uint32_t BhB = sbase + OFF_BH + buf * BSTAGE;
        uint32_t BlB = sbase + OFF_BL + buf * BSTAGE;

#pragma unroll
        for (int ks = 0; ks < 3; ks++) {
            uint32_t ah[2][4], al[2][4];
#pragma unroll
            for (int t = 0; t < 2; t++) {
                uint32_t ao = a_off + t * (16 * ASTB) + ks * 32;
                ldsm4(ah[t], AhB + ao);
                ldsm4(al[t], AlB + ao);
            }
#pragma unroll
            for (int nt2 = 0; nt2 < 7; nt2++) {
                uint32_t bo = b_off + nt2 * (16 * ASTB) + ks * 32;
                uint32_t bh[4], bl[4];
                ldsm4(bh, BhB + bo);
                ldsm4(bl, BlB + bo);
#pragma unroll
                for (int t = 0; t < 2; t++) {
                    MMA_BF16(acc[t][2*nt2],   ah[t][0], ah[t][1], ah[t][2], ah[t][3], bh[0], bh[1]);
                    MMA_BF16(acc[t][2*nt2],   ah[t][0], ah[t][1], ah[t][2], ah[t][3], bl[0], bl[1]);
                    MMA_BF16(acc[t][2*nt2],   al[t][0], al[t][1], al[t][2], al[t][3], bh[0], bh[1]);
                    MMA_BF16(acc[t][2*nt2+1], ah[t][0], ah[t][1], ah[t][2], ah[t][3], bh[2], bh[3]);
                    MMA_BF16(acc[t][2*nt2+1], ah[t][0], ah[t][1], ah[t][2], ah[t][3], bl[2], bl[3]);
                    MMA_BF16(acc[t][2*nt2+1], al[t][0], al[t][1], al[t][2], al[t][3], bh[2], bh[3]);
                }
            }
            {
                uint32_t bo = b2_off + ks * 32;
                uint32_t bh[2], bl[2];
                ldsm2(bh, BhB + bo);
                ldsm2(bl, BlB + bo);
#pragma unroll
                for (int t = 0; t < 2; t++) {
                    MMA_BF16(acc[t][14], ah[t][0], ah[t][1], ah[t][2], ah[t][3], bh[0], bh[1]);
                    MMA_BF16(acc[t][14], ah[t][0], ah[t][1], ah[t][2], ah[t][3], bl[0], bl[1]);
                    MMA_BF16(acc[t][14], al[t][0], al[t][1], al[t][2], al[t][3], bh[0], bh[1]);
                }
            }
        }
        __syncthreads();
    }

#pragma unroll
    for (int t = 0; t < 2; t++) {
        int r0 = wm * 32 + t * 16 + (lane >> 2);
        int r1 = r0 + 8;
        int colb = wn * 120 + (lane & 3) * 2;
        bool ok0 = r0 < mr, ok1 = r1 < mr;
        float w0v = s_w[r0], w1v = s_w[r1];
        float* d0 = ok0 ? &g_part[s_k[r0]][(size_t)s_tok[r0] * DIMV] : 0;
        float* d1 = ok1 ? &g_part[s_k[r1]][(size_t)s_tok[r1] * DIMV] : 0;
#pragma unroll
        for (int nt = 0; nt < 15; nt++) {
            int col = colb + nt * 8;
            if (ok0) {
                float2 o; o.x = w0v * acc[t][nt][0]; o.y = w0v * acc[t][nt][1];
                *(float2*)&d0[col] = o;
            }
            if (ok1) {
                float2 o; o.x = w1v * acc[t][nt][2]; o.y = w1v * acc[t][nt][3];
                *(float2*)&d1[col] = o;
            }
        }
    }
}

// ------------- fused: epilogue(L) [+ gate(L+1)] — wide-access version --------
// warp per token; lane<30 owns d = lane*8 .. lane*8+7 (float4-pair accesses)
template<int DO_GATE>
__global__ void epi_gate_kernel(const float* __restrict__ eb,
                                const float* __restrict__ gamma,
                                const float* __restrict__ beta,
                                const float* __restrict__ gW,
                                const float* __restrict__ gb,
                                int Lnext) {
    int warp = threadIdx.x >> 5;
    int lane = threadIdx.x & 31;
    int tok  = blockIdx.x * 8 + warp;
    bool act = lane < 30;
    int d0i = lane * 8;

    int   e0 = g_route_e[tok * 2 + 0], e1 = g_route_e[tok * 2 + 1];
    float w0 = g_route_w[tok * 2 + 0], w1 = g_route_w[tok * 2 + 1];

    float v[8];
    float sum = 0.f;
    if (act) {
        const float* p0 = &g_part[0][(size_t)tok * DIMV + d0i];
        const float* p1 = &g_part[1][(size_t)tok * DIMV + d0i];
        const float* b0 = &eb[e0 * DIMV + d0i];
        const float* b1 = &eb[e1 * DIMV + d0i];
        float4 p0a = *(const float4*)p0,        p0b = *(const float4*)(p0 + 4);
        float4 p1a = *(const float4*)p1,        p1b = *(const float4*)(p1 + 4);
        float4 b0a = *(const float4*)b0,        b0b = *(const float4*)(b0 + 4);
        float4 b1a = *(const float4*)b1,        b1b = *(const float4*)(b1 + 4);
        v[0] = p0a.x + p1a.x + w0 * b0a.x + w1 * b1a.x;
        v[1] = p0a.y + p1a.y + w0 * b0a.y + w1 * b1a.y;
        v[2] = p0a.z + p1a.z + w0 * b0a.z + w1 * b1a.z;
        v[3] = p0a.w + p1a.w + w0 * b0a.w + w1 * b1a.w;
        v[4] = p0b.x + p1b.x + w0 * b0b.x + w1 * b1b.x;
        v[5] = p0b.y + p1b.y + w0 * b0b.y + w1 * b1b.y;
        v[6] = p0b.z + p1b.z + w0 * b0b.z + w1 * b1b.z;
        v[7] = p0b.w + p1b.w + w0 * b0b.w + w1 * b1b.w;
#pragma unroll
        for (int j = 0; j < 8; j++) sum += v[j];
    } else {
#pragma unroll
        for (int j = 0; j < 8; j++) v[j] = 0.f;
    }
#pragma unroll
    for (int o = 16; o > 0; o >>= 1) sum += __shfl_xor_sync(0xffffffffu, sum, o);
    float mean = sum * (1.0f / DIMV);

    float vs = 0.f;
    if (act) {
#pragma unroll
        for (int j = 0; j < 8; j++) { float c = v[j] - mean; vs += c * c; }
    }
#pragma unroll
    for (int o = 16; o > 0; o >>= 1) vs += __shfl_xor_sync(0xffffffffu, vs, o);
    float inv = 1.0f / sqrtf(vs * (1.0f / DIMV) + LNEPS);

    float hv[8];
    if (act) {
        const float* gm = &gamma[d0i];
        const float* bt = &beta[d0i];
        float4 ga = *(const float4*)gm, gb4 = *(const float4*)(gm + 4);
        float4 ba = *(const float4*)bt, bb4 = *(const float4*)(bt + 4);
        float gmv[8] = {ga.x, ga.y, ga.z, ga.w, gb4.x, gb4.y, gb4.z, gb4.w};
        float btv[8] = {ba.x, ba.y, ba.z, ba.w, bb4.x, bb4.y, bb4.z, bb4.w};
        uint32_t hhp[4], hlp[4];
#pragma unroll
        for (int j = 0; j < 8; j++) {
            float ln = (v[j] - mean) * inv * gmv[j] + btv[j];
            hv[j] = v[j] + ln;
        }
#pragma unroll
        for (int j = 0; j < 4; j++) {
            __nv_bfloat162 hi2 = __floats2bfloat162_rn(hv[2*j], hv[2*j+1]);
            float r0 = hv[2*j]   - __bfloat162float(hi2.x);
            float r1 = hv[2*j+1] - __bfloat162float(hi2.y);
            __nv_bfloat162 lo2 = __floats2bfloat162_rn(r0, r1);
            hhp[j] = *(uint32_t*)&hi2;
            hlp[j] = *(uint32_t*)&lo2;
        }
        *(uint4*)&g_hh[(size_t)tok * DIMV + d0i] = make_uint4(hhp[0], hhp[1], hhp[2], hhp[3]);
        *(uint4*)&g_hl[(size_t)tok * DIMV + d0i] = make_uint4(hlp[0], hlp[1], hlp[2], hlp[3]);
    } else {
#pragma unroll
        for (int j = 0; j < 8; j++) hv[j] = 0.f;
    }

    if (DO_GATE) {
        float acc[8];
#pragma unroll
        for (int e = 0; e < 8; e++) acc[e] = 0.f;
        if (act) {
#pragma unroll
            for (int j = 0; j < 8; j++) {
                const float* gr = &gW[(d0i + j) * 8];
                float4 wA = *(const float4*)gr;
                float4 wB = *(const float4*)(gr + 4);
                float h = hv[j];
                acc[0] += h * wA.x; acc[1] += h * wA.y;
                acc[2] += h * wA.z; acc[3] += h * wA.w;
                acc[4] += h * wB.x; acc[5] += h * wB.y;
                acc[6] += h * wB.z; acc[7] += h * wB.w;
            }
        }
#pragma unroll
        for (int e = 0; e < 8; e++)
#pragma unroll
            for (int o = 16; o > 0; o >>= 1)
                acc[e] += __shfl_xor_sync(0xffffffffu, acc[e], o);
        if (lane == 0) {
            float l[8];
#pragma unroll
            for (int e = 0; e < 8; e++) l[e] = acc[e] + gb[e];
            route_finalize(l, Lnext, tok);
        }
    }
}

// ------------------------- head (h = hi + lo, vectorized) --------------------
__global__ void head_kernel(const float* __restrict__ hW,
                            const float* __restrict__ hb,
                            float* __restrict__ out) {
    int b = blockIdx.x;
    int tid = threadIdx.x;
    const __nv_bfloat16* hh = g_hh + (size_t)b * SS * DIMV;
    const __nv_bfloat16* hl = g_hl + (size_t)b * SS * DIMV;
    float acc = 0.f;
    for (int i = tid * 8; i < SS * DIMV; i += 256 * 8) {
        uint4 ph = *(const uint4*)&hh[i];
        uint4 pl = *(const uint4*)&hl[i];
        const uint32_t* phw = (const uint32_t*)&ph;
        const uint32_t* plw = (const uint32_t*)&pl;
        int dbase = i % DIMV;     // i multiple of 8, rows multiple of 8
#pragma unroll
        for (int j = 0; j < 4; j++) {
            __nv_bfloat162 h2 = *(const __nv_bfloat162*)&phw[j];
            __nv_bfloat162 l2 = *(const __nv_bfloat162*)&plw[j];
            float h0 = __bfloat162float(h2.x) + __bfloat162float(l2.x);
            float h1 = __bfloat162float(h2.y) + __bfloat162float(l2.y);
            acc += h0 * hW[dbase + 2*j] + h1 * hW[dbase + 2*j + 1];
        }
    }
    __shared__ float red[256];
    red[tid] = acc;
    __syncthreads();
    for (int s2 = 128; s2 > 0; s2 >>= 1) {
        if (tid < s2) red[tid] += red[tid + s2];
        __syncthreads();
    }
    if (tid == 0) {
        float z = red[0] * (1.0f / SS) + hb[0];
        out[b] = 1.0f / (1.0f + expf(-z));
    }
}

// ------------------------- launch -------------------------------------------
extern "C" void kernel_launch(void* const* d_in, const int* in_sizes, int n_in,
                              void* d_out, int out_size) {
    const float* x     = (const float*)d_in[0];
    const int*   step  = (const int*)  d_in[1];
    const float* roots = (const float*)d_in[2];
    const float* projW = (const float*)d_in[3];
    const float* gW    = (const float*)d_in[4];
    const float* gb    = (const float*)d_in[5];
    const float* eW    = (const float*)d_in[6];
    const float* ebias = (const float*)d_in[7];
    const float* gamma = (const float*)d_in[8];
    const float* beta  = (const float*)d_in[9];
    const float* hW    = (const float*)d_in[10];
    const float* hb    = (const float*)d_in[11];
    float* out = (float*)d_out;

    cudaFuncSetAttribute(moe_mma_kernel,
                         cudaFuncAttributeMaxDynamicSharedMemorySize, SMEM_DYN);

    setup_kernel<<<240, DIMV>>>(roots, projW);
    {
        dim3 bg(15, NDEPTH * NEXP);
        bconv_kernel<<<bg, 256>>>(eW);
    }
    cycle_kernel<<<NTOK, 256>>>(x, step, gW, gb);

    for (int L = 0; L < NDEPTH; L++) {
        moe_mma_kernel<<<NTILES, 256, SMEM_DYN>>>(L);
        if (L + 1 < NDEPTH) {
            epi_gate_kernel<1><<<NTOK / 8, 256>>>(
                ebias + (size_t)L * NEXP * DIMV, gamma, beta,
                gW + (size_t)(L + 1) * DIMV * NEXP, gb + (size_t)(L + 1) * NEXP,
                L + 1);
        } else {
            epi_gate_kernel<0><<<NTOK / 8, 256>>>(
                ebias + (size_t)L * NEXP * DIMV, gamma, beta,
                gW, gb, 0);
        }
    }

    head_kernel<<<BB, 256>>>(hW, hb, out);
}

// round 14
// speedup vs baseline: 1.1362x; 1.0196x over previous
#include <cuda_runtime.h>
#include <cuda_bf16.h>
#include <math.h>
#include <stdint.h>

#define BB 8
#define SS 2048
#define DIMV 240
#define NTOK (BB*SS)          // 16384
#define NEXP 8
#define NDEPTH 8
#define LATENTV 8
#define LOWD 80
#define LNEPS 1e-5f
#define PI_F 3.14159265358979323846f

// ------------------------- device scratch ----------------------------------
__device__ __nv_bfloat16 g_hh[(size_t)NTOK * DIMV];
__device__ __nv_bfloat16 g_hl[(size_t)NTOK * DIMV];
__device__ float g_part[2][(size_t)NTOK * DIMV];
__device__ int   g_cnt[NDEPTH][NEXP];
__device__ int   g_list_tok[NEXP][NTOK];
__device__ float g_list_w[NEXP][NTOK];
__device__ int   g_list_k[NEXP][NTOK];
__device__ int   g_route_e[NTOK * 2];
__device__ float g_route_w[NTOK * 2];
__device__ float g_ce[240 * DIMV];
__device__ float g_se[240 * DIMV];
__device__ __nv_bfloat16 g_Bth[(size_t)NDEPTH * NEXP * DIMV * DIMV];
__device__ __nv_bfloat16 g_Btl[(size_t)NDEPTH * NEXP * DIMV * DIMV];

// ------------------------- PTX helpers --------------------------------------
__device__ __forceinline__ unsigned smem_u32(const void* p) {
    return (unsigned)__cvta_generic_to_shared(p);
}
__device__ __forceinline__ void cp16(unsigned dst, const void* src) {
    asm volatile("cp.async.ca.shared.global [%0], [%1], 16;\n" :: "r"(dst), "l"(src));
}
__device__ __forceinline__ void cp_commit() {
    asm volatile("cp.async.commit_group;\n" ::: "memory");
}
template<int N>
__device__ __forceinline__ void cp_wait() {
    asm volatile("cp.async.wait_group %0;\n" :: "n"(N) : "memory");
}
__device__ __forceinline__ void ldsm4(uint32_t* r, uint32_t addr) {
    asm volatile("ldmatrix.sync.aligned.m8n8.x4.shared.b16 {%0,%1,%2,%3}, [%4];"
                 : "=r"(r[0]), "=r"(r[1]), "=r"(r[2]), "=r"(r[3]) : "r"(addr));
}
__device__ __forceinline__ void ldsm2(uint32_t* r, uint32_t addr) {
    asm volatile("ldmatrix.sync.aligned.m8n8.x2.shared.b16 {%0,%1}, [%2];"
                 : "=r"(r[0]), "=r"(r[1]) : "r"(addr));
}
#define MMA_BF16(dd, A0, A1, A2, A3, B0, B1)                                   \
    asm volatile("mma.sync.aligned.m16n8k16.row.col.f32.bf16.bf16.f32 "        \
                 "{%0,%1,%2,%3},{%4,%5,%6,%7},{%8,%9},{%0,%1,%2,%3};"          \
                 : "+f"((dd)[0]), "+f"((dd)[1]), "+f"((dd)[2]), "+f"((dd)[3])  \
                 : "r"(A0), "r"(A1), "r"(A2), "r"(A3), "r"(B0), "r"(B1))

// ------------------------- routing finalize (one thread) --------------------
__device__ __forceinline__ void route_finalize(const float l[8], int L, int tok) {
    int e0 = 0; float b0 = l[0];
#pragma unroll
    for (int q = 1; q < 8; q++)
        if (l[q] > b0) { b0 = l[q]; e0 = q; }
    int e1 = -1; float b1 = -1e30f;
#pragma unroll
    for (int q = 0; q < 8; q++)
        if (q != e0 && l[q] > b1) { b1 = l[q]; e1 = q; }

    float w0 = 1.0f / (1.0f + expf(b1 - b0));
    float w1 = 1.0f - w0;

    int p0 = atomicAdd(&g_cnt[L][e0], 1);
    g_list_tok[e0][p0] = tok; g_list_w[e0][p0] = w0; g_list_k[e0][p0] = 0;
    int p1 = atomicAdd(&g_cnt[L][e1], 1);
    g_list_tok[e1][p1] = tok; g_list_w[e1][p1] = w1; g_list_k[e1][p1] = 1;

    g_route_e[tok * 2 + 0] = e0; g_route_e[tok * 2 + 1] = e1;
    g_route_w[tok * 2 + 0] = w0; g_route_w[tok * 2 + 1] = w1;
}

// ------------------------- setup: emb tables + counter zero -----------------
__global__ void setup_kernel(const float* __restrict__ roots,
                             const float* __restrict__ projW) {
    int s = blockIdx.x;
    int d = threadIdx.x;
    int j = d % LOWD;
    float emb = 0.f;
#pragma unroll
    for (int i = 0; i < LATENTV; i++)
        emb += roots[s * LATENTV + i] * projW[i * LOWD + j];
    g_ce[s * DIMV + d] = cosf(emb);
    g_se[s * DIMV + d] = sinf(emb);
    if (blockIdx.x == 0 && d < NDEPTH * NEXP)
        ((int*)g_cnt)[d] = 0;
}

// ------------------------- B convert + transpose ----------------------------
__global__ void bconv_kernel(const float* __restrict__ eW) {
    int le = blockIdx.y;
    int k0 = blockIdx.x * 16;
    const float* W = eW + (size_t)le * DIMV * DIMV;
    __nv_bfloat16* BH = g_Bth + (size_t)le * DIMV * DIMV;
    __nv_bfloat16* BL = g_Btl + (size_t)le * DIMV * DIMV;
    __shared__ float tile[16][241];
    for (int i = threadIdx.x; i < 16 * 240; i += 256) {
        int kk = i / 240, n = i - kk * 240;
        tile[kk][n] = W[(size_t)(k0 + kk) * DIMV + n];
    }
    __syncthreads();
    for (int i = threadIdx.x; i < 240 * 16; i += 256) {
        int n = i >> 4, kk = i & 15;
        float v = tile[kk][n];
        __nv_bfloat16 h = __float2bfloat16(v);
        float r = v - __bfloat162float(h);
        BH[(size_t)n * DIMV + k0 + kk] = h;
        BL[(size_t)n * DIMV + k0 + kk] = __float2bfloat16(r);
    }
}

// ------------------------- cycle block + fused gate(0) ----------------------
__global__ void cycle_kernel(const float* __restrict__ x,
                             const int* __restrict__ step,
                             const float* __restrict__ gW,
                             const float* __restrict__ gb) {
    __shared__ float s_x1[DIMV];
    __shared__ float s_se[DIMV];
    __shared__ float s_pump;
    __shared__ float s_acc[8];
    int t = blockIdx.x;
    int d = threadIdx.x;
    int lane = d & 31;
    int r = (t % SS) % 240;
    if (d == 0) s_pump = 0.8f * sinf((float)(*step) * 0.006f * 2.0f * PI_F);
    if (d < 8) s_acc[d] = 0.f;
    float ce = 0.f, se = 0.f;
    if (d < DIMV) {
        ce = g_ce[r * DIMV + d];
        se = g_se[r * DIMV + d];
        s_se[d] = se;
    }
    __syncthreads();
    if (d < DIMV)
        s_x1[d] = x[(size_t)t * DIMV + d] * (ce + s_pump);
    __syncthreads();

    float h = 0.f;
    if (d < DIMV) {
        int dm1 = (d + DIMV - 1) % DIMV;
        int dm2 = (d + DIMV - 2) % DIMV;
        h = (s_x1[d]
           + s_x1[dm1] * se
           + s_x1[dm2] * s_se[dm1] * ce) * (1.0f / 3.0f);
        __nv_bfloat16 hi = __float2bfloat16(h);
        g_hh[(size_t)t * DIMV + d] = hi;
        g_hl[(size_t)t * DIMV + d] = __float2bfloat16(h - __bfloat162float(hi));
    }

    float p[8];
    if (d < DIMV) {
        float4 w0 = *(const float4*)&gW[d * 8];
        float4 w1 = *(const float4*)&gW[d * 8 + 4];
        p[0] = h * w0.x; p[1] = h * w0.y; p[2] = h * w0.z; p[3] = h * w0.w;
        p[4] = h * w1.x; p[5] = h * w1.y; p[6] = h * w1.z; p[7] = h * w1.w;
    } else {
#pragma unroll
        for (int e = 0; e < 8; e++) p[e] = 0.f;
    }
#pragma unroll
    for (int e = 0; e < 8; e++)
#pragma unroll
        for (int o = 16; o > 0; o >>= 1)
            p[e] += __shfl_xor_sync(0xffffffffu, p[e], o);
    if (lane == 0) {
#pragma unroll
        for (int e = 0; e < 8; e++)
            atomicAdd(&s_acc[e], p[e]);
    }
    __syncthreads();
    if (d == 0) {
        float l[8];
#pragma unroll
        for (int e = 0; e < 8; e++) l[e] = s_acc[e] + gb[e];
        route_finalize(l, 0, t);
    }
}

// ------------------------- tensor-core grouped GEMM (mma.sync bf16) ---------
// R11 best-measured config, verbatim: MT=128, KC=48, 256 thr, ldmatrix.
#define MT 128
#define NTILES (2 * NTOK / MT + NEXP)   // 264
#define KC 48
#define AST 56
#define ASTB (AST * 2)                   // 112 bytes
#define OFF_AH 0
#define OFF_AL 28672
#define OFF_BH 57344
#define OFF_BL 111104
#define SMEM_DYN 164864
#define ASTAGE (MT * ASTB)
#define BSTAGE (DIMV * ASTB)

__global__ __launch_bounds__(256, 1)
void moe_mma_kernel(int L) {
    int tileid = blockIdx.x;
    int e = 0, base = 0, cnt = 0, cum = 0;
#pragma unroll
    for (int q = 0; q < NEXP; q++) {
        int cq = g_cnt[L][q];
        int t = (cq + MT - 1) / MT;
        if (tileid >= cum && tileid < cum + t) { e = q; base = (tileid - cum) * MT; cnt = cq; }
        cum += t;
    }
    if (tileid >= cum) return;
    int mr = min(MT, cnt - base);

    extern __shared__ __align__(16) char dsm[];
    __shared__ int   s_tok[MT];
    __shared__ float s_w[MT];
    __shared__ int   s_k[MT];

    int tid = threadIdx.x, wid = tid >> 5, lane = tid & 31;

    if (tid < MT) {
        if (tid < mr) {
            s_tok[tid] = g_list_tok[e][base + tid];
            s_w[tid]   = g_list_w[e][base + tid];
            s_k[tid]   = g_list_k[e][base + tid];
        } else { s_tok[tid] = 0; s_w[tid] = 0.f; s_k[tid] = 0; }
    }
    __syncthreads();

    const __nv_bfloat16* BHsrc = g_Bth + (size_t)(L * NEXP + e) * DIMV * DIMV;
    const __nv_bfloat16* BLsrc = g_Btl + (size_t)(L * NEXP + e) * DIMV * DIMV;

    auto issue = [&](int kc, int buf) {
        int abuf = buf * ASTAGE;
        int bbuf = buf * BSTAGE;
#pragma unroll
        for (int j = 0; j < 3; j++) {
            int i = tid + j * 256;
            int row = i / 6, seg = i - row * 6;
            size_t src = (size_t)s_tok[row] * DIMV + kc * KC + seg * 8;
            unsigned dst = row * ASTB + seg * 16;
            cp16(smem_u32(dsm + OFF_AH + abuf + dst), g_hh + src);
            cp16(smem_u32(dsm + OFF_AL + abuf + dst), g_hl + src);
        }
        for (int i = tid; i < DIMV * 6; i += 256) {
            int row = i / 6, seg = i - row * 6;
            size_t src = (size_t)row * DIMV + kc * KC + seg * 8;
            unsigned dst = row * ASTB + seg * 16;
            cp16(smem_u32(dsm + OFF_BH + bbuf + dst), BHsrc + src);
            cp16(smem_u32(dsm + OFF_BL + bbuf + dst), BLsrc + src);
        }
        cp_commit();
    };

    int wm = wid & 3;
    int wn = wid >> 2;

    float acc[2][15][4];
#pragma unroll
    for (int t = 0; t < 2; t++)
#pragma unroll
        for (int nt = 0; nt < 15; nt++)
#pragma unroll
            for (int j = 0; j < 4; j++) acc[t][nt][j] = 0.f;

    issue(0, 0);

    uint32_t sbase = smem_u32(dsm);
    uint32_t a_off = (uint32_t)(wm * 32 + (lane & 15)) * ASTB + ((lane >> 4) << 4);
    uint32_t b_off = (uint32_t)(wn * 120 + ((lane >> 4) << 3) + (lane & 7)) * ASTB
                   + (((lane >> 3) & 1) << 4);
    uint32_t b2_off = (uint32_t)(wn * 120 + 112 + (lane & 7)) * ASTB
                    + (((lane >> 3) & 1) << 4);

    for (int kc = 0; kc < 5; kc++) {
        int buf = kc & 1;
        if (kc + 1 < 5) { issue(kc + 1, buf ^ 1); cp_wait<1>(); }
        else            { cp_wait<0>(); }
        __syncthreads();

        uint32_t AhB = sbase + OFF_AH + buf * ASTAGE;
        uint32_t AlB = sbase + OFF_AL + buf * ASTAGE;
        uint32_t BhB = sbase + OFF_BH + buf * BSTAGE;
        uint32_t BlB = sbase + OFF_BL + buf * BSTAGE;

#pragma unroll
        for (int ks = 0; ks < 3; ks++) {
            uint32_t ah[2][4], al[2][4];
#pragma unroll
            for (int t = 0; t < 2; t++) {
                uint32_t ao = a_off + t * (16 * ASTB) + ks * 32;
                ldsm4(ah[t], AhB + ao);
                ldsm4(al[t], AlB + ao);
            }
#pragma unroll
            for (int nt2 = 0; nt2 < 7; nt2++) {
                uint32_t bo = b_off + nt2 * (16 * ASTB) + ks * 32;
                uint32_t bh[4], bl[4];
                ldsm4(bh, BhB + bo);
                ldsm4(bl, BlB + bo);
#pragma unroll
                for (int t = 0; t < 2; t++) {
                    MMA_BF16(acc[t][2*nt2],   ah[t][0], ah[t][1], ah[t][2], ah[t][3], bh[0], bh[1]);
                    MMA_BF16(acc[t][2*nt2],   ah[t][0], ah[t][1], ah[t][2], ah[t][3], bl[0], bl[1]);
                    MMA_BF16(acc[t][2*nt2],   al[t][0], al[t][1], al[t][2], al[t][3], bh[0], bh[1]);
                    MMA_BF16(acc[t][2*nt2+1], ah[t][0], ah[t][1], ah[t][2], ah[t][3], bh[2], bh[3]);
                    MMA_BF16(acc[t][2*nt2+1], ah[t][0], ah[t][1], ah[t][2], ah[t][3], bl[2], bl[3]);
                    MMA_BF16(acc[t][2*nt2+1], al[t][0], al[t][1], al[t][2], al[t][3], bh[2], bh[3]);
                }
            }
            {
                uint32_t bo = b2_off + ks * 32;
                uint32_t bh[2], bl[2];
                ldsm2(bh, BhB + bo);
                ldsm2(bl, BlB + bo);
#pragma unroll
                for (int t = 0; t < 2; t++) {
                    MMA_BF16(acc[t][14], ah[t][0], ah[t][1], ah[t][2], ah[t][3], bh[0], bh[1]);
                    MMA_BF16(acc[t][14], ah[t][0], ah[t][1], ah[t][2], ah[t][3], bl[0], bl[1]);
                    MMA_BF16(acc[t][14], al[t][0], al[t][1], al[t][2], al[t][3], bh[0], bh[1]);
                }
            }
        }
        __syncthreads();
    }

#pragma unroll
    for (int t = 0; t < 2; t++) {
        int r0 = wm * 32 + t * 16 + (lane >> 2);
        int r1 = r0 + 8;
        int colb = wn * 120 + (lane & 3) * 2;
        bool ok0 = r0 < mr, ok1 = r1 < mr;
        float w0v = s_w[r0], w1v = s_w[r1];
        float* d0 = ok0 ? &g_part[s_k[r0]][(size_t)s_tok[r0] * DIMV] : 0;
        float* d1 = ok1 ? &g_part[s_k[r1]][(size_t)s_tok[r1] * DIMV] : 0;
#pragma unroll
        for (int nt = 0; nt < 15; nt++) {
            int col = colb + nt * 8;
            if (ok0) {
                float2 o; o.x = w0v * acc[t][nt][0]; o.y = w0v * acc[t][nt][1];
                *(float2*)&d0[col] = o;
            }
            if (ok1) {
                float2 o; o.x = w1v * acc[t][nt][2]; o.y = w1v * acc[t][nt][3];
                *(float2*)&d1[col] = o;
            }
        }
    }
}

// ------------- fused: epilogue(L) [+ gate(L+1)] — 4 tokens per warp ----------
// grid = NTOK/32 blocks, 256 thr = 8 warps x 4 tokens; lane<30 owns 8 dims.
template<int DO_GATE>
__global__ void epi_gate_kernel(const float* __restrict__ eb,
                                const float* __restrict__ gamma,
                                const float* __restrict__ beta,
                                const float* __restrict__ gW,
                                const float* __restrict__ gb,
                                int Lnext) {
    int warp = threadIdx.x >> 5;
    int lane = threadIdx.x & 31;
    int tokb = blockIdx.x * 32 + warp * 4;
    bool act = lane < 30;
    int d0i = lane * 8;

    // warp-invariant: gamma/beta (loaded once, reused for all 4 tokens)
    float gmv[8], btv[8];
    if (act) {
        float4 ga = *(const float4*)&gamma[d0i], gb4 = *(const float4*)&gamma[d0i + 4];
        float4 ba = *(const float4*)&beta[d0i],  bb4 = *(const float4*)&beta[d0i + 4];
        gmv[0]=ga.x; gmv[1]=ga.y; gmv[2]=ga.z; gmv[3]=ga.w;
        gmv[4]=gb4.x; gmv[5]=gb4.y; gmv[6]=gb4.z; gmv[7]=gb4.w;
        btv[0]=ba.x; btv[1]=ba.y; btv[2]=ba.z; btv[3]=ba.w;
        btv[4]=bb4.x; btv[5]=bb4.y; btv[6]=bb4.z; btv[7]=bb4.w;
    }

    int e0[4], e1[4]; float w0[4], w1[4];
#pragma unroll
    for (int t = 0; t < 4; t++) {
        e0[t] = g_route_e[(tokb + t) * 2 + 0];
        e1[t] = g_route_e[(tokb + t) * 2 + 1];
        w0[t] = g_route_w[(tokb + t) * 2 + 0];
        w1[t] = g_route_w[(tokb + t) * 2 + 1];
    }

    float v[4][8];
    float sum[4] = {0.f, 0.f, 0.f, 0.f};
    if (act) {
#pragma unroll
        for (int t = 0; t < 4; t++) {
            const float* p0 = &g_part[0][(size_t)(tokb + t) * DIMV + d0i];
            const float* p1 = &g_part[1][(size_t)(tokb + t) * DIMV + d0i];
            const float* b0 = &eb[e0[t] * DIMV + d0i];
            const float* b1 = &eb[e1[t] * DIMV + d0i];
            float4 p0a = *(const float4*)p0, p0b = *(const float4*)(p0 + 4);
            float4 p1a = *(const float4*)p1, p1b = *(const float4*)(p1 + 4);
            float4 b0a = *(const float4*)b0, b0b = *(const float4*)(b0 + 4);
            float4 b1a = *(const float4*)b1, b1b = *(const float4*)(b1 + 4);
            v[t][0] = p0a.x + p1a.x + w0[t] * b0a.x + w1[t] * b1a.x;
            v[t][1] = p0a.y + p1a.y + w0[t] * b0a.y + w1[t] * b1a.y;
            v[t][2] = p0a.z + p1a.z + w0[t] * b0a.z + w1[t] * b1a.z;
            v[t][3] = p0a.w + p1a.w + w0[t] * b0a.w + w1[t] * b1a.w;
            v[t][4] = p0b.x + p1b.x + w0[t] * b0b.x + w1[t] * b1b.x;
            v[t][5] = p0b.y + p1b.y + w0[t] * b0b.y + w1[t] * b1b.y;
            v[t][6] = p0b.z + p1b.z + w0[t] * b0b.z + w1[t] * b1b.z;
            v[t][7] = p0b.w + p1b.w + w0[t] * b0b.w + w1[t] * b1b.w;
#pragma unroll
            for (int j = 0; j < 8; j++) sum[t] += v[t][j];
        }
    } else {
#pragma unroll
        for (int t = 0; t < 4; t++)
#pragma unroll
            for (int j = 0; j < 8; j++) v[t][j] = 0.f;
    }
#pragma unroll
    for (int o = 16; o > 0; o >>= 1)
#pragma unroll
        for (int t = 0; t < 4; t++)
            sum[t] += __shfl_xor_sync(0xffffffffu, sum[t], o);

    float vs[4] = {0.f, 0.f, 0.f, 0.f};
    float mean[4];
#pragma unroll
    for (int t = 0; t < 4; t++) mean[t] = sum[t] * (1.0f / DIMV);
    if (act) {
#pragma unroll
        for (int t = 0; t < 4; t++)
#pragma unroll
            for (int j = 0; j < 8; j++) {
                float c = v[t][j] - mean[t]; vs[t] += c * c;
            }
    }
#pragma unroll
    for (int o = 16; o > 0; o >>= 1)
#pragma unroll
        for (int t = 0; t < 4; t++)
            vs[t] += __shfl_xor_sync(0xffffffffu, vs[t], o);

    if (act) {
#pragma unroll
        for (int t = 0; t < 4; t++) {
            float inv = 1.0f / sqrtf(vs[t] * (1.0f / DIMV) + LNEPS);
            uint32_t hhp[4], hlp[4];
#pragma unroll
            for (int j = 0; j < 8; j++) {
                float ln = (v[t][j] - mean[t]) * inv * gmv[j] + btv[j];
                v[t][j] = v[t][j] + ln;          // v now holds next-layer h
            }
#pragma unroll
            for (int j = 0; j < 4; j++) {
                __nv_bfloat162 hi2 = __floats2bfloat162_rn(v[t][2*j], v[t][2*j+1]);
                float r0 = v[t][2*j]   - __bfloat162float(hi2.x);
                float r1 = v[t][2*j+1] - __bfloat162float(hi2.y);
                __nv_bfloat162 lo2 = __floats2bfloat162_rn(r0, r1);
                hhp[j] = *(uint32_t*)&hi2;
                hlp[j] = *(uint32_t*)&lo2;
            }
            *(uint4*)&g_hh[(size_t)(tokb + t) * DIMV + d0i] =
                make_uint4(hhp[0], hhp[1], hhp[2], hhp[3]);
            *(uint4*)&g_hl[(size_t)(tokb + t) * DIMV + d0i] =
                make_uint4(hlp[0], hlp[1], hlp[2], hlp[3]);
        }
    }

    if (DO_GATE) {
        float acc[4][8];
#pragma unroll
        for (int t = 0; t < 4; t++)
#pragma unroll
            for (int e = 0; e < 8; e++) acc[t][e] = 0.f;
        if (act) {
#pragma unroll
            for (int j = 0; j < 8; j++) {
                const float* gr = &gW[(d0i + j) * 8];
                float4 wA = *(const float4*)gr;
                float4 wB = *(const float4*)(gr + 4);
#pragma unroll
                for (int t = 0; t < 4; t++) {
                    float h = v[t][j];
                    acc[t][0] += h * wA.x; acc[t][1] += h * wA.y;
                    acc[t][2] += h * wA.z; acc[t][3] += h * wA.w;
                    acc[t][4] += h * wB.x; acc[t][5] += h * wB.y;
                    acc[t][6] += h * wB.z; acc[t][7] += h * wB.w;
                }
            }
        }
#pragma unroll
        for (int e = 0; e < 8; e++)
#pragma unroll
            for (int o = 16; o > 0; o >>= 1)
#pragma unroll
                for (int t = 0; t < 4; t++)
                    acc[t][e] += __shfl_xor_sync(0xffffffffu, acc[t][e], o);
        if (lane == 0) {
#pragma unroll
            for (int t = 0; t < 4; t++) {
                float l[8];
#pragma unroll
                for (int e = 0; e < 8; e++) l[e] = acc[t][e] + gb[e];
                route_finalize(l, Lnext, tokb + t);
            }
        }
    }
}

// ------------------------- head (h = hi + lo, vectorized) --------------------
__global__ void head_kernel(const float* __restrict__ hW,
                            const float* __restrict__ hb,
                            float* __restrict__ out) {
    int b = blockIdx.x;
    int tid = threadIdx.x;
    const __nv_bfloat16* hh = g_hh + (size_t)b * SS * DIMV;
    const __nv_bfloat16* hl = g_hl + (size_t)b * SS * DIMV;
    float acc = 0.f;
    for (int i = tid * 8; i < SS * DIMV; i += 256 * 8) {
        uint4 ph = *(const uint4*)&hh[i];
        uint4 pl = *(const uint4*)&hl[i];
        const uint32_t* phw = (const uint32_t*)&ph;
        const uint32_t* plw = (const uint32_t*)&pl;
        int dbase = i % DIMV;
#pragma unroll
        for (int j = 0; j < 4; j++) {
            __nv_bfloat162 h2 = *(const __nv_bfloat162*)&phw[j];
            __nv_bfloat162 l2 = *(const __nv_bfloat162*)&plw[j];
            float h0 = __bfloat162float(h2.x) + __bfloat162float(l2.x);
            float h1 = __bfloat162float(h2.y) + __bfloat162float(l2.y);
            acc += h0 * hW[dbase + 2*j] + h1 * hW[dbase + 2*j + 1];
        }
    }
    __shared__ float red[256];
    red[tid] = acc;
    __syncthreads();
    for (int s2 = 128; s2 > 0; s2 >>= 1) {
        if (tid < s2) red[tid] += red[tid + s2];
        __syncthreads();
    }
    if (tid == 0) {
        float z = red[0] * (1.0f / SS) + hb[0];
        out[b] = 1.0f / (1.0f + expf(-z));
    }
}

// ------------------------- launch -------------------------------------------
extern "C" void kernel_launch(void* const* d_in, const int* in_sizes, int n_in,
                              void* d_out, int out_size) {
    const float* x     = (const float*)d_in[0];
    const int*   step  = (const int*)  d_in[1];
    const float* roots = (const float*)d_in[2];
    const float* projW = (const float*)d_in[3];
    const float* gW    = (const float*)d_in[4];
    const float* gb    = (const float*)d_in[5];
    const float* eW    = (const float*)d_in[6];
    const float* ebias = (const float*)d_in[7];
    const float* gamma = (const float*)d_in[8];
    const float* beta  = (const float*)d_in[9];
    const float* hW    = (const float*)d_in[10];
    const float* hb    = (const float*)d_in[11];
    float* out = (float*)d_out;

    cudaFuncSetAttribute(moe_mma_kernel,
                         cudaFuncAttributeMaxDynamicSharedMemorySize, SMEM_DYN);

    setup_kernel<<<240, DIMV>>>(roots, projW);
    {
        dim3 bg(15, NDEPTH * NEXP);
        bconv_kernel<<<bg, 256>>>(eW);
    }
    cycle_kernel<<<NTOK, 256>>>(x, step, gW, gb);

    for (int L = 0; L < NDEPTH; L++) {
        moe_mma_kernel<<<NTILES, 256, SMEM_DYN>>>(L);
        if (L + 1 < NDEPTH) {
            epi_gate_kernel<1><<<NTOK / 32, 256>>>(
                ebias + (size_t)L * NEXP * DIMV, gamma, beta,
                gW + (size_t)(L + 1) * DIMV * NEXP, gb + (size_t)(L + 1) * NEXP,
                L + 1);
        } else {
            epi_gate_kernel<0><<<NTOK / 32, 256>>>(
                ebias + (size_t)L * NEXP * DIMV, gamma, beta,
                gW, gb, 0);
        }
    }

    head_kernel<<<BB, 256>>>(hW, hb, out);
}

// round 15
// speedup vs baseline: 1.1537x; 1.0154x over previous
#include <cuda_runtime.h>
#include <cuda_bf16.h>
#include <math.h>
#include <stdint.h>

#define BB 8
#define SS 2048
#define DIMV 240
#define NTOK (BB*SS)          // 16384
#define NEXP 8
#define NDEPTH 8
#define LATENTV 8
#define LOWD 80
#define LNEPS 1e-5f
#define PI_F 3.14159265358979323846f

// ------------------------- device scratch ----------------------------------
__device__ __nv_bfloat16 g_hh[(size_t)NTOK * DIMV];
__device__ __nv_bfloat16 g_hl[(size_t)NTOK * DIMV];
__device__ float g_part[2][(size_t)NTOK * DIMV];
__device__ int   g_cnt[NDEPTH][NEXP];
__device__ int   g_list_tok[NEXP][NTOK];
__device__ float g_list_w[NEXP][NTOK];
__device__ int   g_list_k[NEXP][NTOK];
__device__ int   g_route_e[NTOK * 2];
__device__ float g_route_w[NTOK * 2];
__device__ float g_ce[240 * DIMV];
__device__ float g_se[240 * DIMV];
__device__ __nv_bfloat16 g_Bth[(size_t)NDEPTH * NEXP * DIMV * DIMV];
__device__ __nv_bfloat16 g_Btl[(size_t)NDEPTH * NEXP * DIMV * DIMV];

// ------------------------- PTX helpers --------------------------------------
__device__ __forceinline__ unsigned smem_u32(const void* p) {
    return (unsigned)__cvta_generic_to_shared(p);
}
__device__ __forceinline__ void cp16(unsigned dst, const void* src) {
    asm volatile("cp.async.ca.shared.global [%0], [%1], 16;\n" :: "r"(dst), "l"(src));
}
__device__ __forceinline__ void cp_commit() {
    asm volatile("cp.async.commit_group;\n" ::: "memory");
}
template<int N>
__device__ __forceinline__ void cp_wait() {
    asm volatile("cp.async.wait_group %0;\n" :: "n"(N) : "memory");
}
__device__ __forceinline__ void ldsm4(uint32_t* r, uint32_t addr) {
    asm volatile("ldmatrix.sync.aligned.m8n8.x4.shared.b16 {%0,%1,%2,%3}, [%4];"
                 : "=r"(r[0]), "=r"(r[1]), "=r"(r[2]), "=r"(r[3]) : "r"(addr));
}
__device__ __forceinline__ void ldsm2(uint32_t* r, uint32_t addr) {
    asm volatile("ldmatrix.sync.aligned.m8n8.x2.shared.b16 {%0,%1}, [%2];"
                 : "=r"(r[0]), "=r"(r[1]) : "r"(addr));
}
#define MMA_BF16(dd, A0, A1, A2, A3, B0, B1)                                   \
    asm volatile("mma.sync.aligned.m16n8k16.row.col.f32.bf16.bf16.f32 "        \
                 "{%0,%1,%2,%3},{%4,%5,%6,%7},{%8,%9},{%0,%1,%2,%3};"          \
                 : "+f"((dd)[0]), "+f"((dd)[1]), "+f"((dd)[2]), "+f"((dd)[3])  \
                 : "r"(A0), "r"(A1), "r"(A2), "r"(A3), "r"(B0), "r"(B1))

// ------------------------- routing finalize (one thread) --------------------
__device__ __forceinline__ void route_finalize(const float l[8], int L, int tok) {
    int e0 = 0; float b0 = l[0];
#pragma unroll
    for (int q = 1; q < 8; q++)
        if (l[q] > b0) { b0 = l[q]; e0 = q; }
    int e1 = -1; float b1 = -1e30f;
#pragma unroll
    for (int q = 0; q < 8; q++)
        if (q != e0 && l[q] > b1) { b1 = l[q]; e1 = q; }

    float w0 = 1.0f / (1.0f + expf(b1 - b0));
    float w1 = 1.0f - w0;

    int p0 = atomicAdd(&g_cnt[L][e0], 1);
    g_list_tok[e0][p0] = tok; g_list_w[e0][p0] = w0; g_list_k[e0][p0] = 0;
    int p1 = atomicAdd(&g_cnt[L][e1], 1);
    g_list_tok[e1][p1] = tok; g_list_w[e1][p1] = w1; g_list_k[e1][p1] = 1;

    g_route_e[tok * 2 + 0] = e0; g_route_e[tok * 2 + 1] = e1;
    g_route_w[tok * 2 + 0] = w0; g_route_w[tok * 2 + 1] = w1;
}

// ------------------------- setup: emb tables + counter zero -----------------
__global__ void setup_kernel(const float* __restrict__ roots,
                             const float* __restrict__ projW) {
    int s = blockIdx.x;
    int d = threadIdx.x;
    int j = d % LOWD;
    float emb = 0.f;
#pragma unroll
    for (int i = 0; i < LATENTV; i++)
        emb += roots[s * LATENTV + i] * projW[i * LOWD + j];
    g_ce[s * DIMV + d] = cosf(emb);
    g_se[s * DIMV + d] = sinf(emb);
    if (blockIdx.x == 0 && d < NDEPTH * NEXP)
        ((int*)g_cnt)[d] = 0;
}

// ------------------------- B convert + transpose (vectorized stores) --------
__global__ void bconv_kernel(const float* __restrict__ eW) {
    int le = blockIdx.y;
    int k0 = blockIdx.x * 16;
    const float* W = eW + (size_t)le * DIMV * DIMV;
    __nv_bfloat16* BH = g_Bth + (size_t)le * DIMV * DIMV;
    __nv_bfloat16* BL = g_Btl + (size_t)le * DIMV * DIMV;
    __shared__ float tile[16][241];
    for (int i = threadIdx.x; i < 16 * 240; i += 256) {
        int kk = i / 240, n = i - kk * 240;
        tile[kk][n] = W[(size_t)(k0 + kk) * DIMV + n];
    }
    __syncthreads();
    int n = threadIdx.x;
    if (n < 240) {
        uint32_t hp[8], lp[8];
#pragma unroll
        for (int q = 0; q < 8; q++) {
            float v0 = tile[2*q][n];
            float v1 = tile[2*q + 1][n];
            __nv_bfloat162 h2 = __floats2bfloat162_rn(v0, v1);
            float r0 = v0 - __bfloat162float(h2.x);
            float r1 = v1 - __bfloat162float(h2.y);
            __nv_bfloat162 l2 = __floats2bfloat162_rn(r0, r1);
            hp[q] = *(uint32_t*)&h2;
            lp[q] = *(uint32_t*)&l2;
        }
        uint4* dh = (uint4*)&BH[(size_t)n * DIMV + k0];
        uint4* dl = (uint4*)&BL[(size_t)n * DIMV + k0];
        dh[0] = make_uint4(hp[0], hp[1], hp[2], hp[3]);
        dh[1] = make_uint4(hp[4], hp[5], hp[6], hp[7]);
        dl[0] = make_uint4(lp[0], lp[1], lp[2], lp[3]);
        dl[1] = make_uint4(lp[4], lp[5], lp[6], lp[7]);
    }
}

// ------------------------- cycle + gate(0): warp per token -------------------
// 256 thr = 8 warps = 8 tokens/block; lane<30 owns d = lane*8..lane*8+7.
__global__ void cycle_kernel(const float* __restrict__ x,
                             const int* __restrict__ step,
                             const float* __restrict__ gW,
                             const float* __restrict__ gb) {
    int warp = threadIdx.x >> 5;
    int lane = threadIdx.x & 31;
    int tok  = blockIdx.x * 8 + warp;
    bool act = lane < 30;
    int d0i  = lane * 8;
    int r = (tok % SS) % 240;

    float pump = 0.8f * sinf((float)(*step) * 0.006f * 2.0f * PI_F);

    float x1[8], se[8], ce[8];
    if (act) {
        const float* xp = &x[(size_t)tok * DIMV + d0i];
        const float* cp = &g_ce[r * DIMV + d0i];
        const float* sp = &g_se[r * DIMV + d0i];
        float4 xa = *(const float4*)xp, xb = *(const float4*)(xp + 4);
        float4 ca = *(const float4*)cp, cb = *(const float4*)(cp + 4);
        float4 sa = *(const float4*)sp, sb = *(const float4*)(sp + 4);
        float xv[8] = {xa.x, xa.y, xa.z, xa.w, xb.x, xb.y, xb.z, xb.w};
        ce[0]=ca.x; ce[1]=ca.y; ce[2]=ca.z; ce[3]=ca.w;
        ce[4]=cb.x; ce[5]=cb.y; ce[6]=cb.z; ce[7]=cb.w;
        se[0]=sa.x; se[1]=sa.y; se[2]=sa.z; se[3]=sa.w;
        se[4]=sb.x; se[5]=sb.y; se[6]=sb.z; se[7]=sb.w;
#pragma unroll
        for (int j = 0; j < 8; j++) x1[j] = xv[j] * (ce[j] + pump);
    } else {
#pragma unroll
        for (int j = 0; j < 8; j++) { x1[j] = 0.f; se[j] = 0.f; ce[j] = 0.f; }
    }

    // ring neighbors from previous lane (lane 0 wraps to lane 29)
    int prev = (lane == 0) ? 29 : lane - 1;
    float px7  = __shfl_sync(0xffffffffu, x1[7], prev);
    float px6  = __shfl_sync(0xffffffffu, x1[6], prev);
    float pse7 = __shfl_sync(0xffffffffu, se[7], prev);

    float hv[8];
    if (act) {
#pragma unroll
        for (int j = 0; j < 8; j++) {
            float xm1 = (j == 0) ? px7 : x1[j - 1];
            float xm2 = (j == 0) ? px6 : ((j == 1) ? px7 : x1[j - 2]);
            float sm1 = (j == 0) ? pse7 : se[j - 1];
            hv[j] = (x1[j] + xm1 * se[j] + xm2 * sm1 * ce[j]) * (1.0f / 3.0f);
        }
        uint32_t hhp[4], hlp[4];
#pragma unroll
        for (int q = 0; q < 4; q++) {
            __nv_bfloat162 hi2 = __floats2bfloat162_rn(hv[2*q], hv[2*q+1]);
            float r0 = hv[2*q]   - __bfloat162float(hi2.x);
            float r1 = hv[2*q+1] - __bfloat162float(hi2.y);
            __nv_bfloat162 lo2 = __floats2bfloat162_rn(r0, r1);
            hhp[q] = *(uint32_t*)&hi2;
            hlp[q] = *(uint32_t*)&lo2;
        }
        *(uint4*)&g_hh[(size_t)tok * DIMV + d0i] = make_uint4(hhp[0], hhp[1], hhp[2], hhp[3]);
        *(uint4*)&g_hl[(size_t)tok * DIMV + d0i] = make_uint4(hlp[0], hlp[1], hlp[2], hlp[3]);
    } else {
#pragma unroll
        for (int j = 0; j < 8; j++) hv[j] = 0.f;
    }

    // gate for layer 0
    float acc[8];
#pragma unroll
    for (int e = 0; e < 8; e++) acc[e] = 0.f;
    if (act) {
#pragma unroll
        for (int j = 0; j < 8; j++) {
            const float* gr = &gW[(d0i + j) * 8];
            float4 wA = *(const float4*)gr;
            float4 wB = *(const float4*)(gr + 4);
            float h = hv[j];
            acc[0] += h * wA.x; acc[1] += h * wA.y;
            acc[2] += h * wA.z; acc[3] += h * wA.w;
            acc[4] += h * wB.x; acc[5] += h * wB.y;
            acc[6] += h * wB.z; acc[7] += h * wB.w;
        }
    }
#pragma unroll
    for (int e = 0; e < 8; e++)
#pragma unroll
        for (int o = 16; o > 0; o >>= 1)
            acc[e] += __shfl_xor_sync(0xffffffffu, acc[e], o);
    if (lane == 0) {
        float l[8];
#pragma unroll
        for (int e = 0; e < 8; e++) l[e] = acc[e] + gb[e];
        route_finalize(l, 0, tok);
    }
}

// ------------------------- tensor-core grouped GEMM (mma.sync bf16) ---------
// R11 best-measured config, verbatim: MT=128, KC=48, 256 thr, ldmatrix.
#define MT 128
#define NTILES (2 * NTOK / MT + NEXP)   // 264
#define KC 48
#define AST 56
#define ASTB (AST * 2)                   // 112 bytes
#define OFF_AH 0
#define OFF_AL 28672
#define OFF_BH 57344
#define OFF_BL 111104
#define SMEM_DYN 164864
#define ASTAGE (MT * ASTB)
#define BSTAGE (DIMV * ASTB)

__global__ __launch_bounds__(256, 1)
void moe_mma_kernel(int L) {
    int tileid = blockIdx.x;
    int e = 0, base = 0, cnt = 0, cum = 0;
#pragma unroll
    for (int q = 0; q < NEXP; q++) {
        int cq = g_cnt[L][q];
        int t = (cq + MT - 1) / MT;
        if (tileid >= cum && tileid < cum + t) { e = q; base = (tileid - cum) * MT; cnt = cq; }
        cum += t;
    }
    if (tileid >= cum) return;
    int mr = min(MT, cnt - base);

    extern __shared__ __align__(16) char dsm[];
    __shared__ int   s_tok[MT];
    __shared__ float s_w[MT];
    __shared__ int   s_k[MT];

    int tid = threadIdx.x, wid = tid >> 5, lane = tid & 31;

    if (tid < MT) {
        if (tid < mr) {
            s_tok[tid] = g_list_tok[e][base + tid];
            s_w[tid]   = g_list_w[e][base + tid];
            s_k[tid]   = g_list_k[e][base + tid];
        } else { s_tok[tid] = 0; s_w[tid] = 0.f; s_k[tid] = 0; }
    }
    __syncthreads();

    const __nv_bfloat16* BHsrc = g_Bth + (size_t)(L * NEXP + e) * DIMV * DIMV;
    const __nv_bfloat16* BLsrc = g_Btl + (size_t)(L * NEXP + e) * DIMV * DIMV;

    auto issue = [&](int kc, int buf) {
        int abuf = buf * ASTAGE;
        int bbuf = buf * BSTAGE;
#pragma unroll
        for (int j = 0; j < 3; j++) {
            int i = tid + j * 256;
            int row = i / 6, seg = i - row * 6;
            size_t src = (size_t)s_tok[row] * DIMV + kc * KC + seg * 8;
            unsigned dst = row * ASTB + seg * 16;
            cp16(smem_u32(dsm + OFF_AH + abuf + dst), g_hh + src);
            cp16(smem_u32(dsm + OFF_AL + abuf + dst), g_hl + src);
        }
        for (int i = tid; i < DIMV * 6; i += 256) {
            int row = i / 6, seg = i - row * 6;
            size_t src = (size_t)row * DIMV + kc * KC + seg * 8;
            unsigned dst = row * ASTB + seg * 16;
            cp16(smem_u32(dsm + OFF_BH + bbuf + dst), BHsrc + src);
            cp16(smem_u32(dsm + OFF_BL + bbuf + dst), BLsrc + src);
        }
        cp_commit();
    };

    int wm = wid & 3;
    int wn = wid >> 2;

    float acc[2][15][4];
#pragma unroll
    for (int t = 0; t < 2; t++)
#pragma unroll
        for (int nt = 0; nt < 15; nt++)
#pragma unroll
            for (int j = 0; j < 4; j++) acc[t][nt][j] = 0.f;

    issue(0, 0);

    uint32_t sbase = smem_u32(dsm);
    uint32_t a_off = (uint32_t)(wm * 32 + (lane & 15)) * ASTB + ((lane >> 4) << 4);
    uint32_t b_off = (uint32_t)(wn * 120 + ((lane >> 4) << 3) + (lane & 7)) * ASTB
                   + (((lane >> 3) & 1) << 4);
    uint32_t b2_off = (uint32_t)(wn * 120 + 112 + (lane & 7)) * ASTB
                    + (((lane >> 3) & 1) << 4);

    for (int kc = 0; kc < 5; kc++) {
        int buf = kc & 1;
        if (kc + 1 < 5) { issue(kc + 1, buf ^ 1); cp_wait<1>(); }
        else            { cp_wait<0>(); }
        __syncthreads();

        uint32_t AhB = sbase + OFF_AH + buf * ASTAGE;
        uint32_t AlB = sbase + OFF_AL + buf * ASTAGE;
        uint32_t BhB = sbase + OFF_BH + buf * BSTAGE;
        uint32_t BlB = sbase + OFF_BL + buf * BSTAGE;

#pragma unroll
        for (int ks = 0; ks < 3; ks++) {
            uint32_t ah[2][4], al[2][4];
#pragma unroll
            for (int t = 0; t < 2; t++) {
                uint32_t ao = a_off + t * (16 * ASTB) + ks * 32;
                ldsm4(ah[t], AhB + ao);
                ldsm4(al[t], AlB + ao);
            }
#pragma unroll
            for (int nt2 = 0; nt2 < 7; nt2++) {
                uint32_t bo = b_off + nt2 * (16 * ASTB) + ks * 32;
                uint32_t bh[4], bl[4];
                ldsm4(bh, BhB + bo);
                ldsm4(bl, BlB + bo);
#pragma unroll
                for (int t = 0; t < 2; t++) {
                    MMA_BF16(acc[t][2*nt2],   ah[t][0], ah[t][1], ah[t][2], ah[t][3], bh[0], bh[1]);
                    MMA_BF16(acc[t][2*nt2],   ah[t][0], ah[t][1], ah[t][2], ah[t][3], bl[0], bl[1]);
                    MMA_BF16(acc[t][2*nt2],   al[t][0], al[t][1], al[t][2], al[t][3], bh[0], bh[1]);
                    MMA_BF16(acc[t][2*nt2+1], ah[t][0], ah[t][1], ah[t][2], ah[t][3], bh[2], bh[3]);
                    MMA_BF16(acc[t][2*nt2+1], ah[t][0], ah[t][1], ah[t][2], ah[t][3], bl[2], bl[3]);
                    MMA_BF16(acc[t][2*nt2+1], al[t][0], al[t][1], al[t][2], al[t][3], bh[2], bh[3]);
                }
            }
            {
                uint32_t bo = b2_off + ks * 32;
                uint32_t bh[2], bl[2];
                ldsm2(bh, BhB + bo);
                ldsm2(bl, BlB + bo);
#pragma unroll
                for (int t = 0; t < 2; t++) {
                    MMA_BF16(acc[t][14], ah[t][0], ah[t][1], ah[t][2], ah[t][3], bh[0], bh[1]);
                    MMA_BF16(acc[t][14], ah[t][0], ah[t][1], ah[t][2], ah[t][3], bl[0], bl[1]);
                    MMA_BF16(acc[t][14], al[t][0], al[t][1], al[t][2], al[t][3], bh[0], bh[1]);
                }
            }
        }
        __syncthreads();
    }

#pragma unroll
    for (int t = 0; t < 2; t++) {
        int r0 = wm * 32 + t * 16 + (lane >> 2);
        int r1 = r0 + 8;
        int colb = wn * 120 + (lane & 3) * 2;
        bool ok0 = r0 < mr, ok1 = r1 < mr;
        float w0v = s_w[r0], w1v = s_w[r1];
        float* d0 = ok0 ? &g_part[s_k[r0]][(size_t)s_tok[r0] * DIMV] : 0;
        float* d1 = ok1 ? &g_part[s_k[r1]][(size_t)s_tok[r1] * DIMV] : 0;
#pragma unroll
        for (int nt = 0; nt < 15; nt++) {
            int col = colb + nt * 8;
            if (ok0) {
                float2 o; o.x = w0v * acc[t][nt][0]; o.y = w0v * acc[t][nt][1];
                *(float2*)&d0[col] = o;
            }
            if (ok1) {
                float2 o; o.x = w1v * acc[t][nt][2]; o.y = w1v * acc[t][nt][3];
                *(float2*)&d1[col] = o;
            }
        }
    }
}

// ------------- fused: epilogue(L) [+ gate(L+1)] — 4 tokens per warp ----------
template<int DO_GATE>
__global__ void epi_gate_kernel(const float* __restrict__ eb,
                                const float* __restrict__ gamma,
                                const float* __restrict__ beta,
                                const float* __restrict__ gW,
                                const float* __restrict__ gb,
                                int Lnext) {
    int warp = threadIdx.x >> 5;
    int lane = threadIdx.x & 31;
    int tokb = blockIdx.x * 32 + warp * 4;
    bool act = lane < 30;
    int d0i = lane * 8;

    float gmv[8], btv[8];
    if (act) {
        float4 ga = *(const float4*)&gamma[d0i], gb4 = *(const float4*)&gamma[d0i + 4];
        float4 ba = *(const float4*)&beta[d0i],  bb4 = *(const float4*)&beta[d0i + 4];
        gmv[0]=ga.x; gmv[1]=ga.y; gmv[2]=ga.z; gmv[3]=ga.w;
        gmv[4]=gb4.x; gmv[5]=gb4.y; gmv[6]=gb4.z; gmv[7]=gb4.w;
        btv[0]=ba.x; btv[1]=ba.y; btv[2]=ba.z; btv[3]=ba.w;
        btv[4]=bb4.x; btv[5]=bb4.y; btv[6]=bb4.z; btv[7]=bb4.w;
    }

    int e0[4], e1[4]; float w0[4], w1[4];
#pragma unroll
    for (int t = 0; t < 4; t++) {
        e0[t] = g_route_e[(tokb + t) * 2 + 0];
        e1[t] = g_route_e[(tokb + t) * 2 + 1];
        w0[t] = g_route_w[(tokb + t) * 2 + 0];
        w1[t] = g_route_w[(tokb + t) * 2 + 1];
    }

    float v[4][8];
    float sum[4] = {0.f, 0.f, 0.f, 0.f};
    if (act) {
#pragma unroll
        for (int t = 0; t < 4; t++) {
            const float* p0 = &g_part[0][(size_t)(tokb + t) * DIMV + d0i];
            const float* p1 = &g_part[1][(size_t)(tokb + t) * DIMV + d0i];
            const float* b0 = &eb[e0[t] * DIMV + d0i];
            const float* b1 = &eb[e1[t] * DIMV + d0i];
            float4 p0a = *(const float4*)p0, p0b = *(const float4*)(p0 + 4);
            float4 p1a = *(const float4*)p1, p1b = *(const float4*)(p1 + 4);
            float4 b0a = *(const float4*)b0, b0b = *(const float4*)(b0 + 4);
            float4 b1a = *(const float4*)b1, b1b = *(const float4*)(b1 + 4);
            v[t][0] = p0a.x + p1a.x + w0[t] * b0a.x + w1[t] * b1a.x;
            v[t][1] = p0a.y + p1a.y + w0[t] * b0a.y + w1[t] * b1a.y;
            v[t][2] = p0a.z + p1a.z + w0[t] * b0a.z + w1[t] * b1a.z;
            v[t][3] = p0a.w + p1a.w + w0[t] * b0a.w + w1[t] * b1a.w;
            v[t][4] = p0b.x + p1b.x + w0[t] * b0b.x + w1[t] * b1b.x;
            v[t][5] = p0b.y + p1b.y + w0[t] * b0b.y + w1[t] * b1b.y;
            v[t][6] = p0b.z + p1b.z + w0[t] * b0b.z + w1[t] * b1b.z;
            v[t][7] = p0b.w + p1b.w + w0[t] * b0b.w + w1[t] * b1b.w;
#pragma unroll
            for (int j = 0; j < 8; j++) sum[t] += v[t][j];
        }
    } else {
#pragma unroll
        for (int t = 0; t < 4; t++)
#pragma unroll
            for (int j = 0; j < 8; j++) v[t][j] = 0.f;
    }
#pragma unroll
    for (int o = 16; o > 0; o >>= 1)
#pragma unroll
        for (int t = 0; t < 4; t++)
            sum[t] += __shfl_xor_sync(0xffffffffu, sum[t], o);

    float vs[4] = {0.f, 0.f, 0.f, 0.f};
    float mean[4];
#pragma unroll
    for (int t = 0; t < 4; t++) mean[t] = sum[t] * (1.0f / DIMV);
    if (act) {
#pragma unroll
        for (int t = 0; t < 4; t++)
#pragma unroll
            for (int j = 0; j < 8; j++) {
                float c = v[t][j] - mean[t]; vs[t] += c * c;
            }
    }
#pragma unroll
    for (int o = 16; o > 0; o >>= 1)
#pragma unroll
        for (int t = 0; t < 4; t++)
            vs[t] += __shfl_xor_sync(0xffffffffu, vs[t], o);

    if (act) {
#pragma unroll
        for (int t = 0; t < 4; t++) {
            float inv = 1.0f / sqrtf(vs[t] * (1.0f / DIMV) + LNEPS);
            uint32_t hhp[4], hlp[4];
#pragma unroll
            for (int j = 0; j < 8; j++) {
                float ln = (v[t][j] - mean[t]) * inv * gmv[j] + btv[j];
                v[t][j] = v[t][j] + ln;
            }
#pragma unroll
            for (int j = 0; j < 4; j++) {
                __nv_bfloat162 hi2 = __floats2bfloat162_rn(v[t][2*j], v[t][2*j+1]);
                float r0 = v[t][2*j]   - __bfloat162float(hi2.x);
                float r1 = v[t][2*j+1] - __bfloat162float(hi2.y);
                __nv_bfloat162 lo2 = __floats2bfloat162_rn(r0, r1);
                hhp[j] = *(uint32_t*)&hi2;
                hlp[j] = *(uint32_t*)&lo2;
            }
            *(uint4*)&g_hh[(size_t)(tokb + t) * DIMV + d0i] =
                make_uint4(hhp[0], hhp[1], hhp[2], hhp[3]);
            *(uint4*)&g_hl[(size_t)(tokb + t) * DIMV + d0i] =
                make_uint4(hlp[0], hlp[1], hlp[2], hlp[3]);
        }
    }

    if (DO_GATE) {
        float acc[4][8];
#pragma unroll
        for (int t = 0; t < 4; t++)
#pragma unroll
            for (int e = 0; e < 8; e++) acc[t][e] = 0.f;
        if (act) {
#pragma unroll
            for (int j = 0; j < 8; j++) {
                const float* gr = &gW[(d0i + j) * 8];
                float4 wA = *(const float4*)gr;
                float4 wB = *(const float4*)(gr + 4);
#pragma unroll
                for (int t = 0; t < 4; t++) {
                    float h = v[t][j];
                    acc[t][0] += h * wA.x; acc[t][1] += h * wA.y;
                    acc[t][2] += h * wA.z; acc[t][3] += h * wA.w;
                    acc[t][4] += h * wB.x; acc[t][5] += h * wB.y;
                    acc[t][6] += h * wB.z; acc[t][7] += h * wB.w;
                }
            }
        }
#pragma unroll
        for (int e = 0; e < 8; e++)
#pragma unroll
            for (int o = 16; o > 0; o >>= 1)
#pragma unroll
                for (int t = 0; t < 4; t++)
                    acc[t][e] += __shfl_xor_sync(0xffffffffu, acc[t][e], o);
        if (lane == 0) {
#pragma unroll
            for (int t = 0; t < 4; t++) {
                float l[8];
#pragma unroll
                for (int e = 0; e < 8; e++) l[e] = acc[t][e] + gb[e];
                route_finalize(l, Lnext, tokb + t);
            }
        }
    }
}

// ------------------------- head (h = hi + lo, vectorized) --------------------
__global__ void head_kernel(const float* __restrict__ hW,
                            const float* __restrict__ hb,
                            float* __restrict__ out) {
    int b = blockIdx.x;
    int tid = threadIdx.x;
    const __nv_bfloat16* hh = g_hh + (size_t)b * SS * DIMV;
    const __nv_bfloat16* hl = g_hl + (size_t)b * SS * DIMV;
    float acc = 0.f;
    for (int i = tid * 8; i < SS * DIMV; i += 256 * 8) {
        uint4 ph = *(const uint4*)&hh[i];
        uint4 pl = *(const uint4*)&hl[i];
        const uint32_t* phw = (const uint32_t*)&ph;
        const uint32_t* plw = (const uint32_t*)&pl;
        int dbase = i % DIMV;
#pragma unroll
        for (int j = 0; j < 4; j++) {
            __nv_bfloat162 h2 = *(const __nv_bfloat162*)&phw[j];
            __nv_bfloat162 l2 = *(const __nv_bfloat162*)&plw[j];
            float h0 = __bfloat162float(h2.x) + __bfloat162float(l2.x);
            float h1 = __bfloat162float(h2.y) + __bfloat162float(l2.y);
            acc += h0 * hW[dbase + 2*j] + h1 * hW[dbase + 2*j + 1];
        }
    }
    __shared__ float red[256];
    red[tid] = acc;
    __syncthreads();
    for (int s2 = 128; s2 > 0; s2 >>= 1) {
        if (tid < s2) red[tid] += red[tid + s2];
        __syncthreads();
    }
    if (tid == 0) {
        float z = red[0] * (1.0f / SS) + hb[0];
        out[b] = 1.0f / (1.0f + expf(-z));
    }
}

// ------------------------- launch -------------------------------------------
extern "C" void kernel_launch(void* const* d_in, const int* in_sizes, int n_in,
                              void* d_out, int out_size) {
    const float* x     = (const float*)d_in[0];
    const int*   step  = (const int*)  d_in[1];
    const float* roots = (const float*)d_in[2];
    const float* projW = (const float*)d_in[3];
    const float* gW    = (const float*)d_in[4];
    const float* gb    = (const float*)d_in[5];
    const float* eW    = (const float*)d_in[6];
    const float* ebias = (const float*)d_in[7];
    const float* gamma = (const float*)d_in[8];
    const float* beta  = (const float*)d_in[9];
    const float* hW    = (const float*)d_in[10];
    const float* hb    = (const float*)d_in[11];
    float* out = (float*)d_out;

    cudaFuncSetAttribute(moe_mma_kernel,
                         cudaFuncAttributeMaxDynamicSharedMemorySize, SMEM_DYN);

    setup_kernel<<<240, DIMV>>>(roots, projW);
    {
        dim3 bg(15, NDEPTH * NEXP);
        bconv_kernel<<<bg, 256>>>(eW);
    }
    cycle_kernel<<<NTOK / 8, 256>>>(x, step, gW, gb);

    for (int L = 0; L < NDEPTH; L++) {
        moe_mma_kernel<<<NTILES, 256, SMEM_DYN>>>(L);
        if (L + 1 < NDEPTH) {
            epi_gate_kernel<1><<<NTOK / 32, 256>>>(
                ebias + (size_t)L * NEXP * DIMV, gamma, beta,
                gW + (size_t)(L + 1) * DIMV * NEXP, gb + (size_t)(L + 1) * NEXP,
                L + 1);
        } else {
            epi_gate_kernel<0><<<NTOK / 32, 256>>>(
                ebias + (size_t)L * NEXP * DIMV, gamma, beta,
                gW, gb, 0);
        }
    }

    head_kernel<<<BB, 256>>>(hW, hb, out);
}

// round 16
// speedup vs baseline: 1.3446x; 1.1655x over previous
#include <cuda_runtime.h>
#include <cuda_bf16.h>
#include <math.h>
#include <stdint.h>

#define BB 8
#define SS 2048
#define DIMV 240
#define NTOK (BB*SS)          // 16384
#define NEXP 8
#define NDEPTH 8
#define LATENTV 8
#define LOWD 80
#define LNEPS 1e-5f
#define PI_F 3.14159265358979323846f

// ------------------------- device scratch ----------------------------------
__device__ __nv_bfloat16 g_hh[(size_t)NTOK * DIMV];
__device__ __nv_bfloat16 g_hl[(size_t)NTOK * DIMV];
__device__ float g_part[2][(size_t)NTOK * DIMV];
__device__ int   g_cnt[NDEPTH][NEXP];
__device__ int   g_list_tok[NEXP][NTOK];
__device__ float g_list_w[NEXP][NTOK];
__device__ int   g_list_k[NEXP][NTOK];
__device__ int   g_route_e[NTOK * 2];
__device__ float g_route_w[NTOK * 2];
__device__ float g_ce[240 * DIMV];
__device__ float g_se[240 * DIMV];
__device__ __nv_bfloat16 g_Bth[(size_t)NDEPTH * NEXP * DIMV * DIMV];
__device__ __nv_bfloat16 g_Btl[(size_t)NDEPTH * NEXP * DIMV * DIMV];

// ------------------------- PTX helpers --------------------------------------
__device__ __forceinline__ unsigned smem_u32(const void* p) {
    return (unsigned)__cvta_generic_to_shared(p);
}
__device__ __forceinline__ void cp16(unsigned dst, const void* src) {
    asm volatile("cp.async.ca.shared.global [%0], [%1], 16;\n" :: "r"(dst), "l"(src));
}
__device__ __forceinline__ void cp_commit() {
    asm volatile("cp.async.commit_group;\n" ::: "memory");
}
template<int N>
__device__ __forceinline__ void cp_wait() {
    asm volatile("cp.async.wait_group %0;\n" :: "n"(N) : "memory");
}
__device__ __forceinline__ void ldsm4(uint32_t* r, uint32_t addr) {
    asm volatile("ldmatrix.sync.aligned.m8n8.x4.shared.b16 {%0,%1,%2,%3}, [%4];"
                 : "=r"(r[0]), "=r"(r[1]), "=r"(r[2]), "=r"(r[3]) : "r"(addr));
}
__device__ __forceinline__ void ldsm2(uint32_t* r, uint32_t addr) {
    asm volatile("ldmatrix.sync.aligned.m8n8.x2.shared.b16 {%0,%1}, [%2];"
                 : "=r"(r[0]), "=r"(r[1]) : "r"(addr));
}
#define MMA_BF16(dd, A0, A1, A2, A3, B0, B1)                                   \
    asm volatile("mma.sync.aligned.m16n8k16.row.col.f32.bf16.bf16.f32 "        \
                 "{%0,%1,%2,%3},{%4,%5,%6,%7},{%8,%9},{%0,%1,%2,%3};"          \
                 : "+f"((dd)[0]), "+f"((dd)[1]), "+f"((dd)[2]), "+f"((dd)[3])  \
                 : "r"(A0), "r"(A1), "r"(A2), "r"(A3), "r"(B0), "r"(B1))

// ---------------- routing: top-2 select + route record (no list write) ------
__device__ __forceinline__ void route_compute(const float l[8], int tok,
                                              int &e0, int &e1,
                                              float &w0, float &w1) {
    e0 = 0; float b0 = l[0];
#pragma unroll
    for (int q = 1; q < 8; q++)
        if (l[q] > b0) { b0 = l[q]; e0 = q; }
    e1 = -1; float b1 = -1e30f;
#pragma unroll
    for (int q = 0; q < 8; q++)
        if (q != e0 && l[q] > b1) { b1 = l[q]; e1 = q; }
    w0 = 1.0f / (1.0f + expf(b1 - b0));
    w1 = 1.0f - w0;
    g_route_e[tok * 2 + 0] = e0; g_route_e[tok * 2 + 1] = e1;
    g_route_w[tok * 2 + 0] = w0; g_route_w[tok * 2 + 1] = w1;
}

// ------------------------- setup: emb tables + counter zero -----------------
__global__ void setup_kernel(const float* __restrict__ roots,
                             const float* __restrict__ projW) {
    int s = blockIdx.x;
    int d = threadIdx.x;
    int j = d % LOWD;
    float emb = 0.f;
#pragma unroll
    for (int i = 0; i < LATENTV; i++)
        emb += roots[s * LATENTV + i] * projW[i * LOWD + j];
    g_ce[s * DIMV + d] = cosf(emb);
    g_se[s * DIMV + d] = sinf(emb);
    if (blockIdx.x == 0 && d < NDEPTH * NEXP)
        ((int*)g_cnt)[d] = 0;
}

// ------------------------- B convert + transpose (vectorized stores) --------
__global__ void bconv_kernel(const float* __restrict__ eW) {
    int le = blockIdx.y;
    int k0 = blockIdx.x * 16;
    const float* W = eW + (size_t)le * DIMV * DIMV;
    __nv_bfloat16* BH = g_Bth + (size_t)le * DIMV * DIMV;
    __nv_bfloat16* BL = g_Btl + (size_t)le * DIMV * DIMV;
    __shared__ float tile[16][241];
    for (int i = threadIdx.x; i < 16 * 240; i += 256) {
        int kk = i / 240, n = i - kk * 240;
        tile[kk][n] = W[(size_t)(k0 + kk) * DIMV + n];
    }
    __syncthreads();
    int n = threadIdx.x;
    if (n < 240) {
        uint32_t hp[8], lp[8];
#pragma unroll
        for (int q = 0; q < 8; q++) {
            float v0 = tile[2*q][n];
            float v1 = tile[2*q + 1][n];
            __nv_bfloat162 h2 = __floats2bfloat162_rn(v0, v1);
            float r0 = v0 - __bfloat162float(h2.x);
            float r1 = v1 - __bfloat162float(h2.y);
            __nv_bfloat162 l2 = __floats2bfloat162_rn(r0, r1);
            hp[q] = *(uint32_t*)&h2;
            lp[q] = *(uint32_t*)&l2;
        }
        uint4* dh = (uint4*)&BH[(size_t)n * DIMV + k0];
        uint4* dl = (uint4*)&BL[(size_t)n * DIMV + k0];
        dh[0] = make_uint4(hp[0], hp[1], hp[2], hp[3]);
        dh[1] = make_uint4(hp[4], hp[5], hp[6], hp[7]);
        dl[0] = make_uint4(lp[0], lp[1], lp[2], lp[3]);
        dl[1] = make_uint4(lp[4], lp[5], lp[6], lp[7]);
    }
}

// ------------------------- cycle + gate(0): warp per token -------------------
// 512 thr = 16 warps = 16 tokens/block; block-aggregated routing counters.
__global__ void cycle_kernel(const float* __restrict__ x,
                             const int* __restrict__ step,
                             const float* __restrict__ gW,
                             const float* __restrict__ gb) {
    __shared__ int   s_cnt[NEXP];
    __shared__ int   s_base[NEXP];
    __shared__ int   s_te[16][2];
    __shared__ float s_tw[16][2];
    __shared__ int   s_pos[16][2];

    int warp = threadIdx.x >> 5;
    int lane = threadIdx.x & 31;
    int tok  = blockIdx.x * 16 + warp;
    bool act = lane < 30;
    int d0i  = lane * 8;
    int r = (tok % SS) % 240;

    if (threadIdx.x < NEXP) s_cnt[threadIdx.x] = 0;
    __syncthreads();

    float pump = 0.8f * sinf((float)(*step) * 0.006f * 2.0f * PI_F);

    float x1[8], se[8], ce[8];
    if (act) {
        const float* xp = &x[(size_t)tok * DIMV + d0i];
        const float* cp = &g_ce[r * DIMV + d0i];
        const float* sp = &g_se[r * DIMV + d0i];
        float4 xa = *(const float4*)xp, xb = *(const float4*)(xp + 4);
        float4 ca = *(const float4*)cp, cb = *(const float4*)(cp + 4);
        float4 sa = *(const float4*)sp, sb = *(const float4*)(sp + 4);
        float xv[8] = {xa.x, xa.y, xa.z, xa.w, xb.x, xb.y, xb.z, xb.w};
        ce[0]=ca.x; ce[1]=ca.y; ce[2]=ca.z; ce[3]=ca.w;
        ce[4]=cb.x; ce[5]=cb.y; ce[6]=cb.z; ce[7]=cb.w;
        se[0]=sa.x; se[1]=sa.y; se[2]=sa.z; se[3]=sa.w;
        se[4]=sb.x; se[5]=sb.y; se[6]=sb.z; se[7]=sb.w;
#pragma unroll
        for (int j = 0; j < 8; j++) x1[j] = xv[j] * (ce[j] + pump);
    } else {
#pragma unroll
        for (int j = 0; j < 8; j++) { x1[j] = 0.f; se[j] = 0.f; ce[j] = 0.f; }
    }

    int prev = (lane == 0) ? 29 : lane - 1;
    float px7  = __shfl_sync(0xffffffffu, x1[7], prev);
    float px6  = __shfl_sync(0xffffffffu, x1[6], prev);
    float pse7 = __shfl_sync(0xffffffffu, se[7], prev);

    float hv[8];
    if (act) {
#pragma unroll
        for (int j = 0; j < 8; j++) {
            float xm1 = (j == 0) ? px7 : x1[j - 1];
            float xm2 = (j == 0) ? px6 : ((j == 1) ? px7 : x1[j - 2]);
            float sm1 = (j == 0) ? pse7 : se[j - 1];
            hv[j] = (x1[j] + xm1 * se[j] + xm2 * sm1 * ce[j]) * (1.0f / 3.0f);
        }
        uint32_t hhp[4], hlp[4];
#pragma unroll
        for (int q = 0; q < 4; q++) {
            __nv_bfloat162 hi2 = __floats2bfloat162_rn(hv[2*q], hv[2*q+1]);
            float r0 = hv[2*q]   - __bfloat162float(hi2.x);
            float r1 = hv[2*q+1] - __bfloat162float(hi2.y);
            __nv_bfloat162 lo2 = __floats2bfloat162_rn(r0, r1);
            hhp[q] = *(uint32_t*)&hi2;
            hlp[q] = *(uint32_t*)&lo2;
        }
        *(uint4*)&g_hh[(size_t)tok * DIMV + d0i] = make_uint4(hhp[0], hhp[1], hhp[2], hhp[3]);
        *(uint4*)&g_hl[(size_t)tok * DIMV + d0i] = make_uint4(hlp[0], hlp[1], hlp[2], hlp[3]);
    } else {
#pragma unroll
        for (int j = 0; j < 8; j++) hv[j] = 0.f;
    }

    float acc[8];
#pragma unroll
    for (int e = 0; e < 8; e++) acc[e] = 0.f;
    if (act) {
#pragma unroll
        for (int j = 0; j < 8; j++) {
            const float* gr = &gW[(d0i + j) * 8];
            float4 wA = *(const float4*)gr;
            float4 wB = *(const float4*)(gr + 4);
            float h = hv[j];
            acc[0] += h * wA.x; acc[1] += h * wA.y;
            acc[2] += h * wA.z; acc[3] += h * wA.w;
            acc[4] += h * wB.x; acc[5] += h * wB.y;
            acc[6] += h * wB.z; acc[7] += h * wB.w;
        }
    }
#pragma unroll
    for (int e = 0; e < 8; e++)
#pragma unroll
        for (int o = 16; o > 0; o >>= 1)
            acc[e] += __shfl_xor_sync(0xffffffffu, acc[e], o);

    if (lane == 0) {
        float l[8];
#pragma unroll
        for (int e = 0; e < 8; e++) l[e] = acc[e] + gb[e];
        int e0, e1; float w0, w1;
        route_compute(l, tok, e0, e1, w0, w1);
        s_te[warp][0] = e0; s_tw[warp][0] = w0;
        s_pos[warp][0] = atomicAdd(&s_cnt[e0], 1);
        s_te[warp][1] = e1; s_tw[warp][1] = w1;
        s_pos[warp][1] = atomicAdd(&s_cnt[e1], 1);
    }
    __syncthreads();
    if (threadIdx.x < NEXP)
        s_base[threadIdx.x] = atomicAdd(&g_cnt[0][threadIdx.x], s_cnt[threadIdx.x]);
    __syncthreads();
    if (threadIdx.x < 32) {
        int slot = threadIdx.x >> 1, k = threadIdx.x & 1;
        int e = s_te[slot][k];
        int p = s_base[e] + s_pos[slot][k];
        int tk = blockIdx.x * 16 + slot;
        g_list_tok[e][p] = tk;
        g_list_w[e][p]   = s_tw[slot][k];
        g_list_k[e][p]   = k;
    }
}

// ------------------------- tensor-core grouped GEMM (mma.sync bf16) ---------
#define MT 128
#define NTILES (2 * NTOK / MT + NEXP)   // 264
#define KC 48
#define AST 56
#define ASTB (AST * 2)                   // 112 bytes
#define OFF_AH 0
#define OFF_AL 28672
#define OFF_BH 57344
#define OFF_BL 111104
#define SMEM_DYN 164864
#define ASTAGE (MT * ASTB)
#define BSTAGE (DIMV * ASTB)

__global__ __launch_bounds__(256, 1)
void moe_mma_kernel(int L) {
    int tileid = blockIdx.x;
    int e = 0, base = 0, cnt = 0, cum = 0;
#pragma unroll
    for (int q = 0; q < NEXP; q++) {
        int cq = g_cnt[L][q];
        int t = (cq + MT - 1) / MT;
        if (tileid >= cum && tileid < cum + t) { e = q; base = (tileid - cum) * MT; cnt = cq; }
        cum += t;
    }
    if (tileid >= cum) return;
    int mr = min(MT, cnt - base);

    extern __shared__ __align__(16) char dsm[];
    __shared__ int   s_tok[MT];
    __shared__ float s_w[MT];
    __shared__ int   s_k[MT];

    int tid = threadIdx.x, wid = tid >> 5, lane = tid & 31;

    if (tid < MT) {
        if (tid < mr) {
            s_tok[tid] = g_list_tok[e][base + tid];
            s_w[tid]   = g_list_w[e][base + tid];
            s_k[tid]   = g_list_k[e][base + tid];
        } else { s_tok[tid] = 0; s_w[tid] = 0.f; s_k[tid] = 0; }
    }
    __syncthreads();

    const __nv_bfloat16* BHsrc = g_Bth + (size_t)(L * NEXP + e) * DIMV * DIMV;
    const __nv_bfloat16* BLsrc = g_Btl + (size_t)(L * NEXP + e) * DIMV * DIMV;

    auto issue = [&](int kc, int buf) {
        int abuf = buf * ASTAGE;
        int bbuf = buf * BSTAGE;
#pragma unroll
        for (int j = 0; j < 3; j++) {
            int i = tid + j * 256;
            int row = i / 6, seg = i - row * 6;
            size_t src = (size_t)s_tok[row] * DIMV + kc * KC + seg * 8;
            unsigned dst = row * ASTB + seg * 16;
            cp16(smem_u32(dsm + OFF_AH + abuf + dst), g_hh + src);
            cp16(smem_u32(dsm + OFF_AL + abuf + dst), g_hl + src);
        }
        for (int i = tid; i < DIMV * 6; i += 256) {
            int row = i / 6, seg = i - row * 6;
            size_t src = (size_t)row * DIMV + kc * KC + seg * 8;
            unsigned dst = row * ASTB + seg * 16;
            cp16(smem_u32(dsm + OFF_BH + bbuf + dst), BHsrc + src);
            cp16(smem_u32(dsm + OFF_BL + bbuf + dst), BLsrc + src);
        }
        cp_commit();
    };

    int wm = wid & 3;
    int wn = wid >> 2;

    float acc[2][15][4];
#pragma unroll
    for (int t = 0; t < 2; t++)
#pragma unroll
        for (int nt = 0; nt < 15; nt++)
#pragma unroll
            for (int j = 0; j < 4; j++) acc[t][nt][j] = 0.f;

    issue(0, 0);

    uint32_t sbase = smem_u32(dsm);
    uint32_t a_off = (uint32_t)(wm * 32 + (lane & 15)) * ASTB + ((lane >> 4) << 4);
    uint32_t b_off = (uint32_t)(wn * 120 + ((lane >> 4) << 3) + (lane & 7)) * ASTB
                   + (((lane >> 3) & 1) << 4);
    uint32_t b2_off = (uint32_t)(wn * 120 + 112 + (lane & 7)) * ASTB
                    + (((lane >> 3) & 1) << 4);

    for (int kc = 0; kc < 5; kc++) {
        int buf = kc & 1;
        if (kc + 1 < 5) { issue(kc + 1, buf ^ 1); cp_wait<1>(); }
        else            { cp_wait<0>(); }
        __syncthreads();

        uint32_t AhB = sbase + OFF_AH + buf * ASTAGE;
        uint32_t AlB = sbase + OFF_AL + buf * ASTAGE;
        uint32_t BhB = sbase + OFF_BH + buf * BSTAGE;
        uint32_t BlB = sbase + OFF_BL + buf * BSTAGE;

#pragma unroll
        for (int ks = 0; ks < 3; ks++) {
            uint32_t ah[2][4], al[2][4];
#pragma unroll
            for (int t = 0; t < 2; t++) {
                uint32_t ao = a_off + t * (16 * ASTB) + ks * 32;
                ldsm4(ah[t], AhB + ao);
                ldsm4(al[t], AlB + ao);
            }
#pragma unroll
            for (int nt2 = 0; nt2 < 7; nt2++) {
                uint32_t bo = b_off + nt2 * (16 * ASTB) + ks * 32;
                uint32_t bh[4], bl[4];
                ldsm4(bh, BhB + bo);
                ldsm4(bl, BlB + bo);
#pragma unroll
                for (int t = 0; t < 2; t++) {
                    MMA_BF16(acc[t][2*nt2],   ah[t][0], ah[t][1], ah[t][2], ah[t][3], bh[0], bh[1]);
                    MMA_BF16(acc[t][2*nt2],   ah[t][0], ah[t][1], ah[t][2], ah[t][3], bl[0], bl[1]);
                    MMA_BF16(acc[t][2*nt2],   al[t][0], al[t][1], al[t][2], al[t][3], bh[0], bh[1]);
                    MMA_BF16(acc[t][2*nt2+1], ah[t][0], ah[t][1], ah[t][2], ah[t][3], bh[2], bh[3]);
                    MMA_BF16(acc[t][2*nt2+1], ah[t][0], ah[t][1], ah[t][2], ah[t][3], bl[2], bl[3]);
                    MMA_BF16(acc[t][2*nt2+1], al[t][0], al[t][1], al[t][2], al[t][3], bh[2], bh[3]);
                }
            }
            {
                uint32_t bo = b2_off + ks * 32;
                uint32_t bh[2], bl[2];
                ldsm2(bh, BhB + bo);
                ldsm2(bl, BlB + bo);
#pragma unroll
                for (int t = 0; t < 2; t++) {
                    MMA_BF16(acc[t][14], ah[t][0], ah[t][1], ah[t][2], ah[t][3], bh[0], bh[1]);
                    MMA_BF16(acc[t][14], ah[t][0], ah[t][1], ah[t][2], ah[t][3], bl[0], bl[1]);
                    MMA_BF16(acc[t][14], al[t][0], al[t][1], al[t][2], al[t][3], bh[0], bh[1]);
                }
            }
        }
        __syncthreads();
    }

#pragma unroll
    for (int t = 0; t < 2; t++) {
        int r0 = wm * 32 + t * 16 + (lane >> 2);
        int r1 = r0 + 8;
        int colb = wn * 120 + (lane & 3) * 2;
        bool ok0 = r0 < mr, ok1 = r1 < mr;
        float w0v = s_w[r0], w1v = s_w[r1];
        float* d0 = ok0 ? &g_part[s_k[r0]][(size_t)s_tok[r0] * DIMV] : 0;
        float* d1 = ok1 ? &g_part[s_k[r1]][(size_t)s_tok[r1] * DIMV] : 0;
#pragma unroll
        for (int nt = 0; nt < 15; nt++) {
            int col = colb + nt * 8;
            if (ok0) {
                float2 o; o.x = w0v * acc[t][nt][0]; o.y = w0v * acc[t][nt][1];
                *(float2*)&d0[col] = o;
            }
            if (ok1) {
                float2 o; o.x = w1v * acc[t][nt][2]; o.y = w1v * acc[t][nt][3];
                *(float2*)&d1[col] = o;
            }
        }
    }
}

// ------------- fused: epilogue(L) [+ gate(L+1)] — 4 tokens per warp ----------
// 256 thr = 8 warps x 4 tokens = 32 tokens/block; block-aggregated counters.
template<int DO_GATE>
__global__ void epi_gate_kernel(const float* __restrict__ eb,
                                const float* __restrict__ gamma,
                                const float* __restrict__ beta,
                                const float* __restrict__ gW,
                                const float* __restrict__ gb,
                                int Lnext) {
    __shared__ int   s_cnt[NEXP];
    __shared__ int   s_base[NEXP];
    __shared__ int   s_te[32][2];
    __shared__ float s_tw[32][2];
    __shared__ int   s_pos[32][2];

    int warp = threadIdx.x >> 5;
    int lane = threadIdx.x & 31;
    int tokb = blockIdx.x * 32 + warp * 4;
    bool act = lane < 30;
    int d0i = lane * 8;

    if (DO_GATE) {
        if (threadIdx.x < NEXP) s_cnt[threadIdx.x] = 0;
        __syncthreads();
    }

    float gmv[8], btv[8];
    if (act) {
        float4 ga = *(const float4*)&gamma[d0i], gb4 = *(const float4*)&gamma[d0i + 4];
        float4 ba = *(const float4*)&beta[d0i],  bb4 = *(const float4*)&beta[d0i + 4];
        gmv[0]=ga.x; gmv[1]=ga.y; gmv[2]=ga.z; gmv[3]=ga.w;
        gmv[4]=gb4.x; gmv[5]=gb4.y; gmv[6]=gb4.z; gmv[7]=gb4.w;
        btv[0]=ba.x; btv[1]=ba.y; btv[2]=ba.z; btv[3]=ba.w;
        btv[4]=bb4.x; btv[5]=bb4.y; btv[6]=bb4.z; btv[7]=bb4.w;
    }

    int e0[4], e1[4]; float w0[4], w1[4];
#pragma unroll
    for (int t = 0; t < 4; t++) {
        e0[t] = g_route_e[(tokb + t) * 2 + 0];
        e1[t] = g_route_e[(tokb + t) * 2 + 1];
        w0[t] = g_route_w[(tokb + t) * 2 + 0];
        w1[t] = g_route_w[(tokb + t) * 2 + 1];
    }

    float v[4][8];
    float sum[4] = {0.f, 0.f, 0.f, 0.f};
    if (act) {
#pragma unroll
        for (int t = 0; t < 4; t++) {
            const float* p0 = &g_part[0][(size_t)(tokb + t) * DIMV + d0i];
            const float* p1 = &g_part[1][(size_t)(tokb + t) * DIMV + d0i];
            const float* b0 = &eb[e0[t] * DIMV + d0i];
            const float* b1 = &eb[e1[t] * DIMV + d0i];
            float4 p0a = *(const float4*)p0, p0b = *(const float4*)(p0 + 4);
            float4 p1a = *(const float4*)p1, p1b = *(const float4*)(p1 + 4);
            float4 b0a = *(const float4*)b0, b0b = *(const float4*)(b0 + 4);
            float4 b1a = *(const float4*)b1, b1b = *(const float4*)(b1 + 4);
            v[t][0] = p0a.x + p1a.x + w0[t] * b0a.x + w1[t] * b1a.x;
            v[t][1] = p0a.y + p1a.y + w0[t] * b0a.y + w1[t] * b1a.y;
            v[t][2] = p0a.z + p1a.z + w0[t] * b0a.z + w1[t] * b1a.z;
            v[t][3] = p0a.w + p1a.w + w0[t] * b0a.w + w1[t] * b1a.w;
            v[t][4] = p0b.x + p1b.x + w0[t] * b0b.x + w1[t] * b1b.x;
            v[t][5] = p0b.y + p1b.y + w0[t] * b0b.y + w1[t] * b1b.y;
            v[t][6] = p0b.z + p1b.z + w0[t] * b0b.z + w1[t] * b1b.z;
            v[t][7] = p0b.w + p1b.w + w0[t] * b0b.w + w1[t] * b1b.w;
#pragma unroll
            for (int j = 0; j < 8; j++) sum[t] += v[t][j];
        }
    } else {
#pragma unroll
        for (int t = 0; t < 4; t++)
#pragma unroll
            for (int j = 0; j < 8; j++) v[t][j] = 0.f;
    }
#pragma unroll
    for (int o = 16; o > 0; o >>= 1)
#pragma unroll
        for (int t = 0; t < 4; t++)
            sum[t] += __shfl_xor_sync(0xffffffffu, sum[t], o);

    float vs[4] = {0.f, 0.f, 0.f, 0.f};
    float mean[4];
#pragma unroll
    for (int t = 0; t < 4; t++) mean[t] = sum[t] * (1.0f / DIMV);
    if (act) {
#pragma unroll
        for (int t = 0; t < 4; t++)
#pragma unroll
            for (int j = 0; j < 8; j++) {
                float c = v[t][j] - mean[t]; vs[t] += c * c;
            }
    }
#pragma unroll
    for (int o = 16; o > 0; o >>= 1)
#pragma unroll
        for (int t = 0; t < 4; t++)
            vs[t] += __shfl_xor_sync(0xffffffffu, vs[t], o);

    if (act) {
#pragma unroll
        for (int t = 0; t < 4; t++) {
            float inv = 1.0f / sqrtf(vs[t] * (1.0f / DIMV) + LNEPS);
            uint32_t hhp[4], hlp[4];
#pragma unroll
            for (int j = 0; j < 8; j++) {
                float ln = (v[t][j] - mean[t]) * inv * gmv[j] + btv[j];
                v[t][j] = v[t][j] + ln;
            }
#pragma unroll
            for (int j = 0; j < 4; j++) {
                __nv_bfloat162 hi2 = __floats2bfloat162_rn(v[t][2*j], v[t][2*j+1]);
                float r0 = v[t][2*j]   - __bfloat162float(hi2.x);
                float r1 = v[t][2*j+1] - __bfloat162float(hi2.y);
                __nv_bfloat162 lo2 = __floats2bfloat162_rn(r0, r1);
                hhp[j] = *(uint32_t*)&hi2;
                hlp[j] = *(uint32_t*)&lo2;
            }
            *(uint4*)&g_hh[(size_t)(tokb + t) * DIMV + d0i] =
                make_uint4(hhp[0], hhp[1], hhp[2], hhp[3]);
            *(uint4*)&g_hl[(size_t)(tokb + t) * DIMV + d0i] =
                make_uint4(hlp[0], hlp[1], hlp[2], hlp[3]);
        }
    }

    if (DO_GATE) {
        float acc[4][8];
#pragma unroll
        for (int t = 0; t < 4; t++)
#pragma unroll
            for (int e = 0; e < 8; e++) acc[t][e] = 0.f;
        if (act) {
#pragma unroll
            for (int j = 0; j < 8; j++) {
                const float* gr = &gW[(d0i + j) * 8];
                float4 wA = *(const float4*)gr;
                float4 wB = *(const float4*)(gr + 4);
#pragma unroll
                for (int t = 0; t < 4; t++) {
                    float h = v[t][j];
                    acc[t][0] += h * wA.x; acc[t][1] += h * wA.y;
                    acc[t][2] += h * wA.z; acc[t][3] += h * wA.w;
                    acc[t][4] += h * wB.x; acc[t][5] += h * wB.y;
                    acc[t][6] += h * wB.z; acc[t][7] += h * wB.w;
                }
            }
        }
#pragma unroll
        for (int e = 0; e < 8; e++)
#pragma unroll
            for (int o = 16; o > 0; o >>= 1)
#pragma unroll
                for (int t = 0; t < 4; t++)
                    acc[t][e] += __shfl_xor_sync(0xffffffffu, acc[t][e], o);

        if (lane == 0) {
#pragma unroll
            for (int t = 0; t < 4; t++) {
                float l[8];
#pragma unroll
                for (int e = 0; e < 8; e++) l[e] = acc[t][e] + gb[e];
                int a0, a1; float u0, u1;
                route_compute(l, tokb + t, a0, a1, u0, u1);
                int slot = warp * 4 + t;
                s_te[slot][0] = a0; s_tw[slot][0] = u0;
                s_pos[slot][0] = atomicAdd(&s_cnt[a0], 1);
                s_te[slot][1] = a1; s_tw[slot][1] = u1;
                s_pos[slot][1] = atomicAdd(&s_cnt[a1], 1);
            }
        }
        __syncthreads();
        if (threadIdx.x < NEXP)
            s_base[threadIdx.x] = atomicAdd(&g_cnt[Lnext][threadIdx.x], s_cnt[threadIdx.x]);
        __syncthreads();
        if (threadIdx.x < 64) {
            int slot = threadIdx.x >> 1, k = threadIdx.x & 1;
            int e = s_te[slot][k];
            int p = s_base[e] + s_pos[slot][k];
            int tk = blockIdx.x * 32 + slot;
            g_list_tok[e][p] = tk;
            g_list_w[e][p]   = s_tw[slot][k];
            g_list_k[e][p]   = k;
        }
    }
}

// ------------------------- head (h = hi + lo, vectorized) --------------------
__global__ void head_kernel(const float* __restrict__ hW,
                            const float* __restrict__ hb,
                            float* __restrict__ out) {
    int b = blockIdx.x;
    int tid = threadIdx.x;
    const __nv_bfloat16* hh = g_hh + (size_t)b * SS * DIMV;
    const __nv_bfloat16* hl = g_hl + (size_t)b * SS * DIMV;
    float acc = 0.f;
    for (int i = tid * 8; i < SS * DIMV; i += 256 * 8) {
        uint4 ph = *(const uint4*)&hh[i];
        uint4 pl = *(const uint4*)&hl[i];
        const uint32_t* phw = (const uint32_t*)&ph;
        const uint32_t* plw = (const uint32_t*)&pl;
        int dbase = i % DIMV;
#pragma unroll
        for (int j = 0; j < 4; j++) {
            __nv_bfloat162 h2 = *(const __nv_bfloat162*)&phw[j];
            __nv_bfloat162 l2 = *(const __nv_bfloat162*)&plw[j];
            float h0 = __bfloat162float(h2.x) + __bfloat162float(l2.x);
            float h1 = __bfloat162float(h2.y) + __bfloat162float(l2.y);
            acc += h0 * hW[dbase + 2*j] + h1 * hW[dbase + 2*j + 1];
        }
    }
    __shared__ float red[256];
    red[tid] = acc;
    __syncthreads();
    for (int s2 = 128; s2 > 0; s2 >>= 1) {
        if (tid < s2) red[tid] += red[tid + s2];
        __syncthreads();
    }
    if (tid == 0) {
        float z = red[0] * (1.0f / SS) + hb[0];
        out[b] = 1.0f / (1.0f + expf(-z));
    }
}

// ------------------------- launch -------------------------------------------
extern "C" void kernel_launch(void* const* d_in, const int* in_sizes, int n_in,
                              void* d_out, int out_size) {
    const float* x     = (const float*)d_in[0];
    const int*   step  = (const int*)  d_in[1];
    const float* roots = (const float*)d_in[2];
    const float* projW = (const float*)d_in[3];
    const float* gW    = (const float*)d_in[4];
    const float* gb    = (const float*)d_in[5];
    const float* eW    = (const float*)d_in[6];
    const float* ebias = (const float*)d_in[7];
    const float* gamma = (const float*)d_in[8];
    const float* beta  = (const float*)d_in[9];
    const float* hW    = (const float*)d_in[10];
    const float* hb    = (const float*)d_in[11];
    float* out = (float*)d_out;

    cudaFuncSetAttribute(moe_mma_kernel,
                         cudaFuncAttributeMaxDynamicSharedMemorySize, SMEM_DYN);

    setup_kernel<<<240, DIMV>>>(roots, projW);
    {
        dim3 bg(15, NDEPTH * NEXP);
        bconv_kernel<<<bg, 256>>>(eW);
    }
    cycle_kernel<<<NTOK / 16, 512>>>(x, step, gW, gb);

    for (int L = 0; L < NDEPTH; L++) {
        moe_mma_kernel<<<NTILES, 256, SMEM_DYN>>>(L);
        if (L + 1 < NDEPTH) {
            epi_gate_kernel<1><<<NTOK / 32, 256>>>(
                ebias + (size_t)L * NEXP * DIMV, gamma, beta,
                gW + (size_t)(L + 1) * DIMV * NEXP, gb + (size_t)(L + 1) * NEXP,
                L + 1);
        } else {
            epi_gate_kernel<0><<<NTOK / 32, 256>>>(
                ebias + (size_t)L * NEXP * DIMV, gamma, beta,
                gW, gb, 0);
        }
    }

    head_kernel<<<BB, 256>>>(hW, hb, out);
}

// round 17
// speedup vs baseline: 1.5099x; 1.1229x over previous
#include <cuda_runtime.h>
#include <cuda_bf16.h>
#include <math.h>
#include <stdint.h>

#define BB 8
#define SS 2048
#define DIMV 240
#define NTOK (BB*SS)          // 16384
#define NEXP 8
#define NDEPTH 8
#define LATENTV 8
#define LOWD 80
#define LNEPS 1e-5f
#define PI_F 3.14159265358979323846f

// ------------------------- device scratch ----------------------------------
__device__ __nv_bfloat16 g_hh[(size_t)NTOK * DIMV];
__device__ __nv_bfloat16 g_hl[(size_t)NTOK * DIMV];
__device__ float g_part[2][(size_t)NTOK * DIMV];
__device__ int   g_cnt[NDEPTH][NEXP];
__device__ int   g_list_tok[NEXP][NTOK];
__device__ float g_list_w[NEXP][NTOK];
__device__ int   g_list_k[NEXP][NTOK];
__device__ int   g_route_e[NTOK * 2];
__device__ float g_route_w[NTOK * 2];
__device__ float g_ce[240 * DIMV];
__device__ float g_se[240 * DIMV];
__device__ __nv_bfloat16 g_Bth[(size_t)NDEPTH * NEXP * DIMV * DIMV];
__device__ __nv_bfloat16 g_Btl[(size_t)NDEPTH * NEXP * DIMV * DIMV];

// ------------------------- PTX helpers --------------------------------------
__device__ __forceinline__ unsigned smem_u32(const void* p) {
    return (unsigned)__cvta_generic_to_shared(p);
}
__device__ __forceinline__ void cp16(unsigned dst, const void* src) {
    asm volatile("cp.async.ca.shared.global [%0], [%1], 16;\n" :: "r"(dst), "l"(src));
}
__device__ __forceinline__ void cp_commit() {
    asm volatile("cp.async.commit_group;\n" ::: "memory");
}
template<int N>
__device__ __forceinline__ void cp_wait() {
    asm volatile("cp.async.wait_group %0;\n" :: "n"(N) : "memory");
}
__device__ __forceinline__ void ldsm4(uint32_t* r, uint32_t addr) {
    asm volatile("ldmatrix.sync.aligned.m8n8.x4.shared.b16 {%0,%1,%2,%3}, [%4];"
                 : "=r"(r[0]), "=r"(r[1]), "=r"(r[2]), "=r"(r[3]) : "r"(addr));
}
__device__ __forceinline__ void ldsm2(uint32_t* r, uint32_t addr) {
    asm volatile("ldmatrix.sync.aligned.m8n8.x2.shared.b16 {%0,%1}, [%2];"
                 : "=r"(r[0]), "=r"(r[1]) : "r"(addr));
}
#define MMA_BF16(dd, A0, A1, A2, A3, B0, B1)                                   \
    asm volatile("mma.sync.aligned.m16n8k16.row.col.f32.bf16.bf16.f32 "        \
                 "{%0,%1,%2,%3},{%4,%5,%6,%7},{%8,%9},{%0,%1,%2,%3};"          \
                 : "+f"((dd)[0]), "+f"((dd)[1]), "+f"((dd)[2]), "+f"((dd)[3])  \
                 : "r"(A0), "r"(A1), "r"(A2), "r"(A3), "r"(B0), "r"(B1))

// ---------------- routing: top-2 select + route record (no list write) ------
__device__ __forceinline__ void route_compute(const float l[8], int tok,
                                              int &e0, int &e1,
                                              float &w0, float &w1) {
    e0 = 0; float b0 = l[0];
#pragma unroll
    for (int q = 1; q < 8; q++)
        if (l[q] > b0) { b0 = l[q]; e0 = q; }
    e1 = -1; float b1 = -1e30f;
#pragma unroll
    for (int q = 0; q < 8; q++)
        if (q != e0 && l[q] > b1) { b1 = l[q]; e1 = q; }
    w0 = 1.0f / (1.0f + expf(b1 - b0));
    w1 = 1.0f - w0;
    g_route_e[tok * 2 + 0] = e0; g_route_e[tok * 2 + 1] = e1;
    g_route_w[tok * 2 + 0] = w0; g_route_w[tok * 2 + 1] = w1;
}

// ------------------------- setup: emb tables + counter zero -----------------
__global__ void setup_kernel(const float* __restrict__ roots,
                             const float* __restrict__ projW) {
    int s = blockIdx.x;
    int d = threadIdx.x;
    int j = d % LOWD;
    float emb = 0.f;
#pragma unroll
    for (int i = 0; i < LATENTV; i++)
        emb += roots[s * LATENTV + i] * projW[i * LOWD + j];
    g_ce[s * DIMV + d] = cosf(emb);
    g_se[s * DIMV + d] = sinf(emb);
    if (blockIdx.x == 0 && d < NDEPTH * NEXP)
        ((int*)g_cnt)[d] = 0;
}

// ------------------------- B convert + transpose (vectorized stores) --------
__global__ void bconv_kernel(const float* __restrict__ eW) {
    int le = blockIdx.y;
    int k0 = blockIdx.x * 16;
    const float* W = eW + (size_t)le * DIMV * DIMV;
    __nv_bfloat16* BH = g_Bth + (size_t)le * DIMV * DIMV;
    __nv_bfloat16* BL = g_Btl + (size_t)le * DIMV * DIMV;
    __shared__ float tile[16][241];
    for (int i = threadIdx.x; i < 16 * 240; i += 256) {
        int kk = i / 240, n = i - kk * 240;
        tile[kk][n] = W[(size_t)(k0 + kk) * DIMV + n];
    }
    __syncthreads();
    int n = threadIdx.x;
    if (n < 240) {
        uint32_t hp[8], lp[8];
#pragma unroll
        for (int q = 0; q < 8; q++) {
            float v0 = tile[2*q][n];
            float v1 = tile[2*q + 1][n];
            __nv_bfloat162 h2 = __floats2bfloat162_rn(v0, v1);
            float r0 = v0 - __bfloat162float(h2.x);
            float r1 = v1 - __bfloat162float(h2.y);
            __nv_bfloat162 l2 = __floats2bfloat162_rn(r0, r1);
            hp[q] = *(uint32_t*)&h2;
            lp[q] = *(uint32_t*)&l2;
        }
        uint4* dh = (uint4*)&BH[(size_t)n * DIMV + k0];
        uint4* dl = (uint4*)&BL[(size_t)n * DIMV + k0];
        dh[0] = make_uint4(hp[0], hp[1], hp[2], hp[3]);
        dh[1] = make_uint4(hp[4], hp[5], hp[6], hp[7]);
        dl[0] = make_uint4(lp[0], lp[1], lp[2], lp[3]);
        dl[1] = make_uint4(lp[4], lp[5], lp[6], lp[7]);
    }
}

// ------------------------- cycle + gate(0): warp per token -------------------
// 512 thr = 16 warps = 16 tokens/block; block-aggregated routing counters.
__global__ void cycle_kernel(const float* __restrict__ x,
                             const int* __restrict__ step,
                             const float* __restrict__ gW,
                             const float* __restrict__ gb) {
    __shared__ int   s_cnt[NEXP];
    __shared__ int   s_base[NEXP];
    __shared__ int   s_te[16][2];
    __shared__ float s_tw[16][2];
    __shared__ int   s_pos[16][2];

    int warp = threadIdx.x >> 5;
    int lane = threadIdx.x & 31;
    int tok  = blockIdx.x * 16 + warp;
    bool act = lane < 30;
    int d0i  = lane * 8;
    int r = (tok % SS) % 240;

    if (threadIdx.x < NEXP) s_cnt[threadIdx.x] = 0;
    __syncthreads();

    float pump = 0.8f * sinf((float)(*step) * 0.006f * 2.0f * PI_F);

    float x1[8], se[8], ce[8];
    if (act) {
        const float* xp = &x[(size_t)tok * DIMV + d0i];
        const float* cp = &g_ce[r * DIMV + d0i];
        const float* sp = &g_se[r * DIMV + d0i];
        float4 xa = *(const float4*)xp, xb = *(const float4*)(xp + 4);
        float4 ca = *(const float4*)cp, cb = *(const float4*)(cp + 4);
        float4 sa = *(const float4*)sp, sb = *(const float4*)(sp + 4);
        float xv[8] = {xa.x, xa.y, xa.z, xa.w, xb.x, xb.y, xb.z, xb.w};
        ce[0]=ca.x; ce[1]=ca.y; ce[2]=ca.z; ce[3]=ca.w;
        ce[4]=cb.x; ce[5]=cb.y; ce[6]=cb.z; ce[7]=cb.w;
        se[0]=sa.x; se[1]=sa.y; se[2]=sa.z; se[3]=sa.w;
        se[4]=sb.x; se[5]=sb.y; se[6]=sb.z; se[7]=sb.w;
#pragma unroll
        for (int j = 0; j < 8; j++) x1[j] = xv[j] * (ce[j] + pump);
    } else {
#pragma unroll
        for (int j = 0; j < 8; j++) { x1[j] = 0.f; se[j] = 0.f; ce[j] = 0.f; }
    }

    int prev = (lane == 0) ? 29 : lane - 1;
    float px7  = __shfl_sync(0xffffffffu, x1[7], prev);
    float px6  = __shfl_sync(0xffffffffu, x1[6], prev);
    float pse7 = __shfl_sync(0xffffffffu, se[7], prev);

    float hv[8];
    if (act) {
#pragma unroll
        for (int j = 0; j < 8; j++) {
            float xm1 = (j == 0) ? px7 : x1[j - 1];
            float xm2 = (j == 0) ? px6 : ((j == 1) ? px7 : x1[j - 2]);
            float sm1 = (j == 0) ? pse7 : se[j - 1];
            hv[j] = (x1[j] + xm1 * se[j] + xm2 * sm1 * ce[j]) * (1.0f / 3.0f);
        }
        uint32_t hhp[4], hlp[4];
#pragma unroll
        for (int q = 0; q < 4; q++) {
            __nv_bfloat162 hi2 = __floats2bfloat162_rn(hv[2*q], hv[2*q+1]);
            float r0 = hv[2*q]   - __bfloat162float(hi2.x);
            float r1 = hv[2*q+1] - __bfloat162float(hi2.y);
            __nv_bfloat162 lo2 = __floats2bfloat162_rn(r0, r1);
            hhp[q] = *(uint32_t*)&hi2;
            hlp[q] = *(uint32_t*)&lo2;
        }
        *(uint4*)&g_hh[(size_t)tok * DIMV + d0i] = make_uint4(hhp[0], hhp[1], hhp[2], hhp[3]);
        *(uint4*)&g_hl[(size_t)tok * DIMV + d0i] = make_uint4(hlp[0], hlp[1], hlp[2], hlp[3]);
    } else {
#pragma unroll
        for (int j = 0; j < 8; j++) hv[j] = 0.f;
    }

    float acc[8];
#pragma unroll
    for (int e = 0; e < 8; e++) acc[e] = 0.f;
    if (act) {
#pragma unroll
        for (int j = 0; j < 8; j++) {
            const float* gr = &gW[(d0i + j) * 8];
            float4 wA = *(const float4*)gr;
            float4 wB = *(const float4*)(gr + 4);
            float h = hv[j];
            acc[0] += h * wA.x; acc[1] += h * wA.y;
            acc[2] += h * wA.z; acc[3] += h * wA.w;
            acc[4] += h * wB.x; acc[5] += h * wB.y;
            acc[6] += h * wB.z; acc[7] += h * wB.w;
        }
    }
#pragma unroll
    for (int e = 0; e < 8; e++)
#pragma unroll
        for (int o = 16; o > 0; o >>= 1)
            acc[e] += __shfl_xor_sync(0xffffffffu, acc[e], o);

    if (lane == 0) {
        float l[8];
#pragma unroll
        for (int e = 0; e < 8; e++) l[e] = acc[e] + gb[e];
        int e0, e1; float w0, w1;
        route_compute(l, tok, e0, e1, w0, w1);
        s_te[warp][0] = e0; s_tw[warp][0] = w0;
        s_pos[warp][0] = atomicAdd(&s_cnt[e0], 1);
        s_te[warp][1] = e1; s_tw[warp][1] = w1;
        s_pos[warp][1] = atomicAdd(&s_cnt[e1], 1);
    }
    __syncthreads();
    if (threadIdx.x < NEXP)
        s_base[threadIdx.x] = atomicAdd(&g_cnt[0][threadIdx.x], s_cnt[threadIdx.x]);
    __syncthreads();
    if (threadIdx.x < 32) {
        int slot = threadIdx.x >> 1, k = threadIdx.x & 1;
        int e = s_te[slot][k];
        int p = s_base[e] + s_pos[slot][k];
        int tk = blockIdx.x * 16 + slot;
        g_list_tok[e][p] = tk;
        g_list_w[e][p]   = s_tw[slot][k];
        g_list_k[e][p]   = k;
    }
}

// ------------------------- tensor-core grouped GEMM (mma.sync bf16) ---------
// 2-term split: Ah·Bh + Ah·Bl (B exact, A bf16-hi only). MT=128, KC=48.
#define MT 128
#define NTILES (2 * NTOK / MT + NEXP)   // 264
#define KC 48
#define AST 56
#define ASTB (AST * 2)                   // 112 bytes
#define OFF_AH 0                         // [2][128][56] bf16 = 28672
#define OFF_BH 28672                     // [2][240][56] bf16 = 53760
#define OFF_BL 82432
#define SMEM_DYN 136192
#define ASTAGE (MT * ASTB)
#define BSTAGE (DIMV * ASTB)

__global__ __launch_bounds__(256, 1)
void moe_mma_kernel(int L) {
    int tileid = blockIdx.x;
    int e = 0, base = 0, cnt = 0, cum = 0;
#pragma unroll
    for (int q = 0; q < NEXP; q++) {
        int cq = g_cnt[L][q];
        int t = (cq + MT - 1) / MT;
        if (tileid >= cum && tileid < cum + t) { e = q; base = (tileid - cum) * MT; cnt = cq; }
        cum += t;
    }
    if (tileid >= cum) return;
    int mr = min(MT, cnt - base);

    extern __shared__ __align__(16) char dsm[];
    __shared__ int   s_tok[MT];
    __shared__ float s_w[MT];
    __shared__ int   s_k[MT];

    int tid = threadIdx.x, wid = tid >> 5, lane = tid & 31;

    if (tid < MT) {
        if (tid < mr) {
            s_tok[tid] = g_list_tok[e][base + tid];
            s_w[tid]   = g_list_w[e][base + tid];
            s_k[tid]   = g_list_k[e][base + tid];
        } else { s_tok[tid] = 0; s_w[tid] = 0.f; s_k[tid] = 0; }
    }
    __syncthreads();

    const __nv_bfloat16* BHsrc = g_Bth + (size_t)(L * NEXP + e) * DIMV * DIMV;
    const __nv_bfloat16* BLsrc = g_Btl + (size_t)(L * NEXP + e) * DIMV * DIMV;

    auto issue = [&](int kc, int buf) {
        int abuf = buf * ASTAGE;
        int bbuf = buf * BSTAGE;
#pragma unroll
        for (int j = 0; j < 3; j++) {                 // A hi only: 768 cp16
            int i = tid + j * 256;
            int row = i / 6, seg = i - row * 6;
            size_t src = (size_t)s_tok[row] * DIMV + kc * KC + seg * 8;
            unsigned dst = row * ASTB + seg * 16;
            cp16(smem_u32(dsm + OFF_AH + abuf + dst), g_hh + src);
        }
        for (int i = tid; i < DIMV * 6; i += 256) {   // B hi + lo
            int row = i / 6, seg = i - row * 6;
            size_t src = (size_t)row * DIMV + kc * KC + seg * 8;
            unsigned dst = row * ASTB + seg * 16;
            cp16(smem_u32(dsm + OFF_BH + bbuf + dst), BHsrc + src);
            cp16(smem_u32(dsm + OFF_BL + bbuf + dst), BLsrc + src);
        }
        cp_commit();
    };

    int wm = wid & 3;
    int wn = wid >> 2;

    float acc[2][15][4];
#pragma unroll
    for (int t = 0; t < 2; t++)
#pragma unroll
        for (int nt = 0; nt < 15; nt++)
#pragma unroll
            for (int j = 0; j < 4; j++) acc[t][nt][j] = 0.f;

    issue(0, 0);

    uint32_t sbase = smem_u32(dsm);
    uint32_t a_off = (uint32_t)(wm * 32 + (lane & 15)) * ASTB + ((lane >> 4) << 4);
    uint32_t b_off = (uint32_t)(wn * 120 + ((lane >> 4) << 3) + (lane & 7)) * ASTB
                   + (((lane >> 3) & 1) << 4);
    uint32_t b2_off = (uint32_t)(wn * 120 + 112 + (lane & 7)) * ASTB
                    + (((lane >> 3) & 1) << 4);

    for (int kc = 0; kc < 5; kc++) {
        int buf = kc & 1;
        if (kc + 1 < 5) { issue(kc + 1, buf ^ 1); cp_wait<1>(); }
        else            { cp_wait<0>(); }
        __syncthreads();

        uint32_t AhB = sbase + OFF_AH + buf * ASTAGE;
        uint32_t BhB = sbase + OFF_BH + buf * BSTAGE;
        uint32_t BlB = sbase + OFF_BL + buf * BSTAGE;

#pragma unroll
        for (int ks = 0; ks < 3; ks++) {
            uint32_t ah[2][4];
#pragma unroll
            for (int t = 0; t < 2; t++) {
                uint32_t ao = a_off + t * (16 * ASTB) + ks * 32;
                ldsm4(ah[t], AhB + ao);
            }
#pragma unroll
            for (int nt2 = 0; nt2 < 7; nt2++) {
                uint32_t bo = b_off + nt2 * (16 * ASTB) + ks * 32;
                uint32_t bh[4], bl[4];
                ldsm4(bh, BhB + bo);
                ldsm4(bl, BlB + bo);
#pragma unroll
                for (int t = 0; t < 2; t++) {
                    MMA_BF16(acc[t][2*nt2],   ah[t][0], ah[t][1], ah[t][2], ah[t][3], bh[0], bh[1]);
                    MMA_BF16(acc[t][2*nt2],   ah[t][0], ah[t][1], ah[t][2], ah[t][3], bl[0], bl[1]);
                    MMA_BF16(acc[t][2*nt2+1], ah[t][0], ah[t][1], ah[t][2], ah[t][3], bh[2], bh[3]);
                    MMA_BF16(acc[t][2*nt2+1], ah[t][0], ah[t][1], ah[t][2], ah[t][3], bl[2], bl[3]);
                }
            }
            {
                uint32_t bo = b2_off + ks * 32;
                uint32_t bh[2], bl[2];
                ldsm2(bh, BhB + bo);
                ldsm2(bl, BlB + bo);
#pragma unroll
                for (int t = 0; t < 2; t++) {
                    MMA_BF16(acc[t][14], ah[t][0], ah[t][1], ah[t][2], ah[t][3], bh[0], bh[1]);
                    MMA_BF16(acc[t][14], ah[t][0], ah[t][1], ah[t][2], ah[t][3], bl[0], bl[1]);
                }
            }
        }
        __syncthreads();
    }

#pragma unroll
    for (int t = 0; t < 2; t++) {
        int r0 = wm * 32 + t * 16 + (lane >> 2);
        int r1 = r0 + 8;
        int colb = wn * 120 + (lane & 3) * 2;
        bool ok0 = r0 < mr, ok1 = r1 < mr;
        float w0v = s_w[r0], w1v = s_w[r1];
        float* d0 = ok0 ? &g_part[s_k[r0]][(size_t)s_tok[r0] * DIMV] : 0;
        float* d1 = ok1 ? &g_part[s_k[r1]][(size_t)s_tok[r1] * DIMV] : 0;
#pragma unroll
        for (int nt = 0; nt < 15; nt++) {
            int col = colb + nt * 8;
            if (ok0) {
                float2 o; o.x = w0v * acc[t][nt][0]; o.y = w0v * acc[t][nt][1];
                *(float2*)&d0[col] = o;
            }
            if (ok1) {
                float2 o; o.x = w1v * acc[t][nt][2]; o.y = w1v * acc[t][nt][3];
                *(float2*)&d1[col] = o;
            }
        }
    }
}

// ------------- fused: epilogue(L) [+ gate(L+1)] — 4 tokens per warp ----------
template<int DO_GATE>
__global__ void epi_gate_kernel(const float* __restrict__ eb,
                                const float* __restrict__ gamma,
                                const float* __restrict__ beta,
                                const float* __restrict__ gW,
                                const float* __restrict__ gb,
                                int Lnext) {
    __shared__ int   s_cnt[NEXP];
    __shared__ int   s_base[NEXP];
    __shared__ int   s_te[32][2];
    __shared__ float s_tw[32][2];
    __shared__ int   s_pos[32][2];

    int warp = threadIdx.x >> 5;
    int lane = threadIdx.x & 31;
    int tokb = blockIdx.x * 32 + warp * 4;
    bool act = lane < 30;
    int d0i = lane * 8;

    if (DO_GATE) {
        if (threadIdx.x < NEXP) s_cnt[threadIdx.x] = 0;
        __syncthreads();
    }

    float gmv[8], btv[8];
    if (act) {
        float4 ga = *(const float4*)&gamma[d0i], gb4 = *(const float4*)&gamma[d0i + 4];
        float4 ba = *(const float4*)&beta[d0i],  bb4 = *(const float4*)&beta[d0i + 4];
        gmv[0]=ga.x; gmv[1]=ga.y; gmv[2]=ga.z; gmv[3]=ga.w;
        gmv[4]=gb4.x; gmv[5]=gb4.y; gmv[6]=gb4.z; gmv[7]=gb4.w;
        btv[0]=ba.x; btv[1]=ba.y; btv[2]=ba.z; btv[3]=ba.w;
        btv[4]=bb4.x; btv[5]=bb4.y; btv[6]=bb4.z; btv[7]=bb4.w;
    }

    int e0[4], e1[4]; float w0[4], w1[4];
#pragma unroll
    for (int t = 0; t < 4; t++) {
        e0[t] = g_route_e[(tokb + t) * 2 + 0];
        e1[t] = g_route_e[(tokb + t) * 2 + 1];
        w0[t] = g_route_w[(tokb + t) * 2 + 0];
        w1[t] = g_route_w[(tokb + t) * 2 + 1];
    }

    float v[4][8];
    float sum[4] = {0.f, 0.f, 0.f, 0.f};
    if (act) {
#pragma unroll
        for (int t = 0; t < 4; t++) {
            const float* p0 = &g_part[0][(size_t)(tokb + t) * DIMV + d0i];
            const float* p1 = &g_part[1][(size_t)(tokb + t) * DIMV + d0i];
            const float* b0 = &eb[e0[t] * DIMV + d0i];
            const float* b1 = &eb[e1[t] * DIMV + d0i];
            float4 p0a = *(const float4*)p0, p0b = *(const float4*)(p0 + 4);
            float4 p1a = *(const float4*)p1, p1b = *(const float4*)(p1 + 4);
            float4 b0a = *(const float4*)b0, b0b = *(const float4*)(b0 + 4);
            float4 b1a = *(const float4*)b1, b1b = *(const float4*)(b1 + 4);
            v[t][0] = p0a.x + p1a.x + w0[t] * b0a.x + w1[t] * b1a.x;
            v[t][1] = p0a.y + p1a.y + w0[t] * b0a.y + w1[t] * b1a.y;
            v[t][2] = p0a.z + p1a.z + w0[t] * b0a.z + w1[t] * b1a.z;
            v[t][3] = p0a.w + p1a.w + w0[t] * b0a.w + w1[t] * b1a.w;
            v[t][4] = p0b.x + p1b.x + w0[t] * b0b.x + w1[t] * b1b.x;
            v[t][5] = p0b.y + p1b.y + w0[t] * b0b.y + w1[t] * b1b.y;
            v[t][6] = p0b.z + p1b.z + w0[t] * b0b.z + w1[t] * b1b.z;
            v[t][7] = p0b.w + p1b.w + w0[t] * b0b.w + w1[t] * b1b.w;
#pragma unroll
            for (int j = 0; j < 8; j++) sum[t] += v[t][j];
        }
    } else {
#pragma unroll
        for (int t = 0; t < 4; t++)
#pragma unroll
            for (int j = 0; j < 8; j++) v[t][j] = 0.f;
    }
#pragma unroll
    for (int o = 16; o > 0; o >>= 1)
#pragma unroll
        for (int t = 0; t < 4; t++)
            sum[t] += __shfl_xor_sync(0xffffffffu, sum[t], o);

    float vs[4] = {0.f, 0.f, 0.f, 0.f};
    float mean[4];
#pragma unroll
    for (int t = 0; t < 4; t++) mean[t] = sum[t] * (1.0f / DIMV);
    if (act) {
#pragma unroll
        for (int t = 0; t < 4; t++)
#pragma unroll
            for (int j = 0; j < 8; j++) {
                float c = v[t][j] - mean[t]; vs[t] += c * c;
            }
    }
#pragma unroll
    for (int o = 16; o > 0; o >>= 1)
#pragma unroll
        for (int t = 0; t < 4; t++)
            vs[t] += __shfl_xor_sync(0xffffffffu, vs[t], o);

    if (act) {
#pragma unroll
        for (int t = 0; t < 4; t++) {
            float inv = 1.0f / sqrtf(vs[t] * (1.0f / DIMV) + LNEPS);
            uint32_t hhp[4], hlp[4];
#pragma unroll
            for (int j = 0; j < 8; j++) {
                float ln = (v[t][j] - mean[t]) * inv * gmv[j] + btv[j];
                v[t][j] = v[t][j] + ln;
            }
#pragma unroll
            for (int j = 0; j < 4; j++) {
                __nv_bfloat162 hi2 = __floats2bfloat162_rn(v[t][2*j], v[t][2*j+1]);
                float r0 = v[t][2*j]   - __bfloat162float(hi2.x);
                float r1 = v[t][2*j+1] - __bfloat162float(hi2.y);
                __nv_bfloat162 lo2 = __floats2bfloat162_rn(r0, r1);
                hhp[j] = *(uint32_t*)&hi2;
                hlp[j] = *(uint32_t*)&lo2;
            }
            *(uint4*)&g_hh[(size_t)(tokb + t) * DIMV + d0i] =
                make_uint4(hhp[0], hhp[1], hhp[2], hhp[3]);
            *(uint4*)&g_hl[(size_t)(tokb + t) * DIMV + d0i] =
                make_uint4(hlp[0], hlp[1], hlp[2], hlp[3]);
        }
    }

    if (DO_GATE) {
        float acc[4][8];
#pragma unroll
        for (int t = 0; t < 4; t++)
#pragma unroll
            for (int e = 0; e < 8; e++) acc[t][e] = 0.f;
        if (act) {
#pragma unroll
            for (int j = 0; j < 8; j++) {
                const float* gr = &gW[(d0i + j) * 8];
                float4 wA = *(const float4*)gr;
                float4 wB = *(const float4*)(gr + 4);
#pragma unroll
                for (int t = 0; t < 4; t++) {
                    float h = v[t][j];
                    acc[t][0] += h * wA.x; acc[t][1] += h * wA.y;
                    acc[t][2] += h * wA.z; acc[t][3] += h * wA.w;
                    acc[t][4] += h * wB.x; acc[t][5] += h * wB.y;
                    acc[t][6] += h * wB.z; acc[t][7] += h * wB.w;
                }
            }
        }
#pragma unroll
        for (int e = 0; e < 8; e++)
#pragma unroll
            for (int o = 16; o > 0; o >>= 1)
#pragma unroll
                for (int t = 0; t < 4; t++)
                    acc[t][e] += __shfl_xor_sync(0xffffffffu, acc[t][e], o);

        if (lane == 0) {
#pragma unroll
            for (int t = 0; t < 4; t++) {
                float l[8];
#pragma unroll
                for (int e = 0; e < 8; e++) l[e] = acc[t][e] + gb[e];
                int a0, a1; float u0, u1;
                route_compute(l, tokb + t, a0, a1, u0, u1);
                int slot = warp * 4 + t;
                s_te[slot][0] = a0; s_tw[slot][0] = u0;
                s_pos[slot][0] = atomicAdd(&s_cnt[a0], 1);
                s_te[slot][1] = a1; s_tw[slot][1] = u1;
                s_pos[slot][1] = atomicAdd(&s_cnt[a1], 1);
            }
        }
        __syncthreads();
        if (threadIdx.x < NEXP)
            s_base[threadIdx.x] = atomicAdd(&g_cnt[Lnext][threadIdx.x], s_cnt[threadIdx.x]);
        __syncthreads();
        if (threadIdx.x < 64) {
            int slot = threadIdx.x >> 1, k = threadIdx.x & 1;
            int e = s_te[slot][k];
            int p = s_base[e] + s_pos[slot][k];
            int tk = blockIdx.x * 32 + slot;
            g_list_tok[e][p] = tk;
            g_list_w[e][p]   = s_tw[slot][k];
            g_list_k[e][p]   = k;
        }
    }
}

// ------------------------- head (h = hi + lo, vectorized) --------------------
__global__ void head_kernel(const float* __restrict__ hW,
                            const float* __restrict__ hb,
                            float* __restrict__ out) {
    int b = blockIdx.x;
    int tid = threadIdx.x;
    const __nv_bfloat16* hh = g_hh + (size_t)b * SS * DIMV;
    const __nv_bfloat16* hl = g_hl + (size_t)b * SS * DIMV;
    float acc = 0.f;
    for (int i = tid * 8; i < SS * DIMV; i += 256 * 8) {
        uint4 ph = *(const uint4*)&hh[i];
        uint4 pl = *(const uint4*)&hl[i];
        const uint32_t* phw = (const uint32_t*)&ph;
        const uint32_t* plw = (const uint32_t*)&pl;
        int dbase = i % DIMV;
#pragma unroll
        for (int j = 0; j < 4; j++) {
            __nv_bfloat162 h2 = *(const __nv_bfloat162*)&phw[j];
            __nv_bfloat162 l2 = *(const __nv_bfloat162*)&plw[j];
            float h0 = __bfloat162float(h2.x) + __bfloat162float(l2.x);
            float h1 = __bfloat162float(h2.y) + __bfloat162float(l2.y);
            acc += h0 * hW[dbase + 2*j] + h1 * hW[dbase + 2*j + 1];
        }
    }
    __shared__ float red[256];
    red[tid] = acc;
    __syncthreads();
    for (int s2 = 128; s2 > 0; s2 >>= 1) {
        if (tid < s2) red[tid] += red[tid + s2];
        __syncthreads();
    }
    if (tid == 0) {
        float z = red[0] * (1.0f / SS) + hb[0];
        out[b] = 1.0f / (1.0f + expf(-z));
    }
}

// ------------------------- launch -------------------------------------------
extern "C" void kernel_launch(void* const* d_in, const int* in_sizes, int n_in,
                              void* d_out, int out_size) {
    const float* x     = (const float*)d_in[0];
    const int*   step  = (const int*)  d_in[1];
    const float* roots = (const float*)d_in[2];
    const float* projW = (const float*)d_in[3];
    const float* gW    = (const float*)d_in[4];
    const float* gb    = (const float*)d_in[5];
    const float* eW    = (const float*)d_in[6];
    const float* ebias = (const float*)d_in[7];
    const float* gamma = (const float*)d_in[8];
    const float* beta  = (const float*)d_in[9];
    const float* hW    = (const float*)d_in[10];
    const float* hb    = (const float*)d_in[11];
    float* out = (float*)d_out;

    cudaFuncSetAttribute(moe_mma_kernel,
                         cudaFuncAttributeMaxDynamicSharedMemorySize, SMEM_DYN);

    setup_kernel<<<240, DIMV>>>(roots, projW);
    {
        dim3 bg(15, NDEPTH * NEXP);
        bconv_kernel<<<bg, 256>>>(eW);
    }
    cycle_kernel<<<NTOK / 16, 512>>>(x, step, gW, gb);

    for (int L = 0; L < NDEPTH; L++) {
        moe_mma_kernel<<<NTILES, 256, SMEM_DYN>>>(L);
        if (L + 1 < NDEPTH) {
            epi_gate_kernel<1><<<NTOK / 32, 256>>>(
                ebias + (size_t)L * NEXP * DIMV, gamma, beta,
                gW + (size_t)(L + 1) * DIMV * NEXP, gb + (size_t)(L + 1) * NEXP,
                L + 1);
        } else {
            epi_gate_kernel<0><<<NTOK / 32, 256>>>(
                ebias + (size_t)L * NEXP * DIMV, gamma, beta,
                gW, gb, 0);
        }
    }

    head_kernel<<<BB, 256>>>(hW, hb, out);
}